// round 12
// baseline (speedup 1.0000x reference)
#include <cuda_runtime.h>
#include <cuda_fp16.h>
#include <math.h>

#define BSZ 32
#define SEQ 1024
#define EMB 768
#define HD  64

typedef unsigned long long ull;
typedef unsigned int uint32;

__device__ __forceinline__ ull pk2(float lo, float hi) {
    ull r; asm("mov.b64 %0, {%1, %2};" : "=l"(r) : "f"(lo), "f"(hi)); return r;
}
__device__ __forceinline__ void upk2(ull v, float& lo, float& hi) {
    asm("mov.b64 {%0, %1}, %2;" : "=f"(lo), "=f"(hi) : "l"(v));
}
__device__ __forceinline__ ull fma2(ull a, ull b, ull c) {
    ull d; asm("fma.rn.f32x2 %0, %1, %2, %3;" : "=l"(d) : "l"(a), "l"(b), "l"(c)); return d;
}
__device__ __forceinline__ ull mul2(ull a, ull b) {
    ull d; asm("mul.rn.f32x2 %0, %1, %2;" : "=l"(d) : "l"(a), "l"(b)); return d;
}
__device__ __forceinline__ uint32 ph2(float lo, float hi) {
    uint32 r; asm("cvt.rn.f16x2.f32 %0, %1, %2;" : "=r"(r) : "f"(hi), "f"(lo)); return r;
}
__device__ __forceinline__ void mma_f16(float c[4],
    uint32 a0, uint32 a1, uint32 a2, uint32 a3, uint32 b0, uint32 b1)
{
    asm volatile(
        "mma.sync.aligned.m16n8k16.row.col.f32.f16.f16.f32 "
        "{%0,%1,%2,%3}, {%4,%5,%6,%7}, {%8,%9}, {%0,%1,%2,%3};"
        : "+f"(c[0]), "+f"(c[1]), "+f"(c[2]), "+f"(c[3])
        : "r"(a0), "r"(a1), "r"(a2), "r"(a3), "r"(b0), "r"(b1));
}

__device__ float g_q[BSZ * SEQ * HD];
__device__ float g_k[BSZ * SEQ * HD];
__device__ float g_v[BSZ * SEQ * HD];
__device__ float g_cos[SEQ * 32];
__device__ float g_sin[SEQ * 32];

// ---------------------------------------------------------------------------
// Kernel 0: RoPE cos/sin table
// ---------------------------------------------------------------------------
__global__ void rope_table_kernel()
{
    const int t = blockIdx.x * blockDim.x + threadIdx.x;
    if (t >= SEQ * 32) return;
    const int pos = t >> 5;
    const int pr  = t & 31;
    const float theta = expf((float)pr * -0.5756462732485114f);
    float sn, cs;
    sincosf((float)pos * theta, &sn, &cs);
    g_cos[t] = cs;
    g_sin[t] = sn;
}

// ---------------------------------------------------------------------------
// Kernel 1: HYBRID QKV projection.
//   grid = (3, 256). Tiles with by < NH_TILES use fp16 HMMA (tensor pipe);
//   the rest use packed-f32x2 FFMA (fma pipe). Both CTA types co-resident.
// ---------------------------------------------------------------------------
#define XW 20          // HMMA smem words/row
#define NH_TILES 190   // tensor:fma split ~ 200:68 MAC rates
// dyn smem: HMMA path 2*128*XW + 2*64*XW words = 30720 B; FFMA2 path 24960 B.
#define QKV_SMEM 30720

__global__ __launch_bounds__(256) void qkv_kernel(
    const float* __restrict__ x,
    const float* __restrict__ Wq,
    const float* __restrict__ Wk,
    const float* __restrict__ Wv)
{
    extern __shared__ char dynsm[];

    const int which = blockIdx.x;
    const float* __restrict__ W = (which == 0) ? Wq : ((which == 1) ? Wk : Wv);
    float* __restrict__ outp    = (which == 0) ? g_q : ((which == 1) ? g_k : g_v);

    const int by = blockIdx.y;
    const int m0 = by * 128;
    const int tid = threadIdx.x;

    if (by < NH_TILES) {
        // ================= fp16 HMMA path (R8) =================
        uint32* xs = (uint32*)dynsm;           // [2][128*XW]
        uint32* ws = xs + 2 * 128 * XW;        // [2][64*XW]

        const int lane   = tid & 31;
        const int wid    = tid >> 5;
        const int warp_m = wid & 3;
        const int warp_n = wid >> 2;
        const int lr = lane >> 2;
        const int lc = lane & 3;

        const int xrow = tid >> 3;
        const int xkq  = tid & 7;

        uint2 rx[4], rw[2];

        float c[2][4][4];
        #pragma unroll
        for (int mt = 0; mt < 2; mt++)
            #pragma unroll
            for (int nt = 0; nt < 4; nt++)
                #pragma unroll
                for (int r = 0; r < 4; r++) c[mt][nt][r] = 0.f;

        #pragma unroll
        for (int q = 0; q < 4; q++) {
            float4 t = *(const float4*)&x[(size_t)(m0 + xrow + q * 32) * EMB + xkq * 4];
            rx[q] = make_uint2(ph2(t.x, t.y), ph2(t.z, t.w));
        }
        #pragma unroll
        for (int q = 0; q < 2; q++) {
            float4 t = *(const float4*)&W[(size_t)(xrow + q * 32) * EMB + xkq * 4];
            rw[q] = make_uint2(ph2(t.x, t.y), ph2(t.z, t.w));
        }
        #pragma unroll
        for (int q = 0; q < 4; q++)
            *(uint2*)&xs[(xrow + q * 32) * XW + xkq * 2] = rx[q];
        #pragma unroll
        for (int q = 0; q < 2; q++)
            *(uint2*)&ws[(xrow + q * 32) * XW + xkq * 2] = rw[q];
        __syncthreads();

        const int NCH = EMB / 32;   // 24
        for (int ec = 0; ec < NCH; ec++) {
            const int cur = ec & 1;
            const bool more = (ec + 1 < NCH);
            if (more) {
                const int e1 = (ec + 1) * 32;
                #pragma unroll
                for (int q = 0; q < 4; q++) {
                    float4 t = *(const float4*)&x[(size_t)(m0 + xrow + q * 32) * EMB + e1 + xkq * 4];
                    rx[q] = make_uint2(ph2(t.x, t.y), ph2(t.z, t.w));
                }
                #pragma unroll
                for (int q = 0; q < 2; q++) {
                    float4 t = *(const float4*)&W[(size_t)(xrow + q * 32) * EMB + e1 + xkq * 4];
                    rw[q] = make_uint2(ph2(t.x, t.y), ph2(t.z, t.w));
                }
            }

            uint32* xc = xs + cur * 128 * XW;
            uint32* wc = ws + cur * 64 * XW;
            #pragma unroll
            for (int ks = 0; ks < 2; ks++) {
                const int kb = ks * 8;
                uint32 a[2][4];
                #pragma unroll
                for (int mt = 0; mt < 2; mt++) {
                    const int rb = warp_m * 32 + mt * 16 + lr;
                    a[mt][0] = xc[rb * XW + kb + lc];
                    a[mt][1] = xc[(rb + 8) * XW + kb + lc];
                    a[mt][2] = xc[rb * XW + kb + lc + 4];
                    a[mt][3] = xc[(rb + 8) * XW + kb + lc + 4];
                }
                uint32 bb[4][2];
                #pragma unroll
                for (int nt = 0; nt < 4; nt++) {
                    const int nb = warp_n * 32 + nt * 8 + lr;
                    bb[nt][0] = wc[nb * XW + kb + lc];
                    bb[nt][1] = wc[nb * XW + kb + lc + 4];
                }
                #pragma unroll
                for (int mt = 0; mt < 2; mt++)
                    #pragma unroll
                    for (int nt = 0; nt < 4; nt++)
                        mma_f16(c[mt][nt], a[mt][0], a[mt][1], a[mt][2], a[mt][3],
                                bb[nt][0], bb[nt][1]);
            }

            if (more) {
                const int nxt = cur ^ 1;
                uint32* xn = xs + nxt * 128 * XW;
                uint32* wn = ws + nxt * 64 * XW;
                #pragma unroll
                for (int q = 0; q < 4; q++)
                    *(uint2*)&xn[(xrow + q * 32) * XW + xkq * 2] = rx[q];
                #pragma unroll
                for (int q = 0; q < 2; q++)
                    *(uint2*)&wn[(xrow + q * 32) * XW + xkq * 2] = rw[q];
                __syncthreads();
            }
        }

        if (which < 2) {
            #pragma unroll
            for (int mt = 0; mt < 2; mt++) {
                const int r0 = m0 + warp_m * 32 + mt * 16 + lr;
                const int r1 = r0 + 8;
                const int p0 = r0 & (SEQ - 1);
                const int p1 = r1 & (SEQ - 1);
                #pragma unroll
                for (int nt = 0; nt < 4; nt++) {
                    const int d0   = warp_n * 32 + nt * 8 + 2 * lc;
                    const int pair = d0 >> 1;
                    {
                        const float cs = g_cos[p0 * 32 + pair];
                        const float sn = g_sin[p0 * 32 + pair];
                        const float av = c[mt][nt][0], bv = c[mt][nt][1];
                        *(ull*)&outp[(size_t)r0 * HD + d0] = pk2(av * cs - bv * sn, bv * cs + av * sn);
                    }
                    {
                        const float cs = g_cos[p1 * 32 + pair];
                        const float sn = g_sin[p1 * 32 + pair];
                        const float av = c[mt][nt][2], bv = c[mt][nt][3];
                        *(ull*)&outp[(size_t)r1 * HD + d0] = pk2(av * cs - bv * sn, bv * cs + av * sn);
                    }
                }
            }
        } else {
            #pragma unroll
            for (int mt = 0; mt < 2; mt++) {
                const int r0 = m0 + warp_m * 32 + mt * 16 + lr;
                #pragma unroll
                for (int nt = 0; nt < 4; nt++) {
                    const int d0 = warp_n * 32 + nt * 8 + 2 * lc;
                    *(ull*)&outp[(size_t)r0 * HD + d0]       = pk2(c[mt][nt][0], c[mt][nt][1]);
                    *(ull*)&outp[(size_t)(r0 + 8) * HD + d0] = pk2(c[mt][nt][2], c[mt][nt][3]);
                }
            }
        }
    } else {
        // ================= packed f32x2 FFMA path (R4) =================
        float* xsf = (float*)dynsm;            // [32][130]
        float* wsf = xsf + 32 * 130;           // [32][65]

        const int tx   = tid & 15;
        const int ty   = tid >> 4;
        const int lcol = tid & 31;
        const int lrow = tid >> 5;

        ull acc2[4][4];
        #pragma unroll
        for (int i = 0; i < 4; i++)
            #pragma unroll
            for (int j = 0; j < 4; j++) acc2[i][j] = 0ull;

        for (int e0 = 0; e0 < EMB; e0 += 32) {
            #pragma unroll
            for (int p = 0; p < 16; p++) {
                const int r = lrow + p * 8;
                xsf[lcol * 130 + r] = x[(size_t)(m0 + r) * EMB + e0 + lcol];
            }
            #pragma unroll
            for (int p = 0; p < 8; p++) {
                const int h = lrow + p * 8;
                wsf[lcol * 65 + h] = W[(size_t)h * EMB + e0 + lcol];
            }
            __syncthreads();

            #pragma unroll
            for (int kk = 0; kk < 32; kk++) {
                const ull* ap = (const ull*)&xsf[kk * 130 + ty * 8];
                ull a2[4];
                #pragma unroll
                for (int i2 = 0; i2 < 4; i2++) a2[i2] = ap[i2];
                ull b2[4];
                #pragma unroll
                for (int j = 0; j < 4; j++) {
                    const float bv = wsf[kk * 65 + tx * 4 + j];
                    b2[j] = pk2(bv, bv);
                }
                #pragma unroll
                for (int i2 = 0; i2 < 4; i2++)
                    #pragma unroll
                    for (int j = 0; j < 4; j++)
                        acc2[i2][j] = fma2(a2[i2], b2[j], acc2[i2][j]);
            }
            __syncthreads();
        }

        if (which < 2) {
            #pragma unroll
            for (int i2 = 0; i2 < 4; i2++) {
                const int r0 = m0 + ty * 8 + 2 * i2;
                const int p0 = r0 & (SEQ - 1);
                const int p1 = (r0 + 1) & (SEQ - 1);
                #pragma unroll
                for (int jp = 0; jp < 2; jp++) {
                    const int pair = tx * 2 + jp;
                    const int d    = tx * 4 + 2 * jp;
                    const ull cs2 = pk2(g_cos[p0 * 32 + pair], g_cos[p1 * 32 + pair]);
                    const ull sn2 = pk2(g_sin[p0 * 32 + pair], g_sin[p1 * 32 + pair]);
                    float s0, s1; upk2(sn2, s0, s1);
                    const ull nsn2 = pk2(-s0, -s1);
                    const ull a = acc2[i2][2 * jp + 0];
                    const ull b = acc2[i2][2 * jp + 1];
                    const ull o0 = fma2(b, nsn2, mul2(a, cs2));
                    const ull o1 = fma2(b, cs2,  mul2(a, sn2));
                    float o0l, o0h, o1l, o1h;
                    upk2(o0, o0l, o0h); upk2(o1, o1l, o1h);
                    *(ull*)&outp[(size_t)r0 * HD + d]       = pk2(o0l, o1l);
                    *(ull*)&outp[(size_t)(r0 + 1) * HD + d] = pk2(o0h, o1h);
                }
            }
        } else {
            #pragma unroll
            for (int i2 = 0; i2 < 4; i2++) {
                const int r0 = m0 + ty * 8 + 2 * i2;
                float v0[4], v1[4];
                #pragma unroll
                for (int j = 0; j < 4; j++) upk2(acc2[i2][j], v0[j], v1[j]);
                *(float4*)&outp[(size_t)r0 * HD + tx * 4]       = make_float4(v0[0], v0[1], v0[2], v0[3]);
                *(float4*)&outp[(size_t)(r0 + 1) * HD + tx * 4] = make_float4(v1[0], v1[1], v1[2], v1[3]);
            }
        }
    }
}

// ---------------------------------------------------------------------------
// Kernel 2: causal flash attention — fp16 m16n8k16, register-resident P (R11).
// ---------------------------------------------------------------------------
#define AW 36

__global__ __launch_bounds__(128) void attn_kernel(float* __restrict__ out)
{
    extern __shared__ uint32 smu[];
    uint32* Ks = smu;                     // [2][64 kv][36w]
    uint32* Vp = Ks + 2 * 64 * AW;        // [2][64 h][36w]

    const int b  = blockIdx.y;
    const int qt = (SEQ / 64 - 1) - blockIdx.x;
    const int q0 = qt * 64;

    const float* __restrict__ qp = g_q + ((size_t)b * SEQ + q0) * HD;
    const float* __restrict__ kp = g_k + (size_t)b * SEQ * HD;
    const float* __restrict__ vp = g_v + (size_t)b * SEQ * HD;

    const int tid  = threadIdx.x;
    const int lane = tid & 31;
    const int w    = tid >> 5;
    const int lr   = lane >> 2;
    const int lc   = lane & 3;

    uint2  rk[8];
    uint32 rv[4][4];

    const float sc2 = 0.03608439182435161f * 1.4426950408889634f;

    uint32 qa[4][4];
    {
        const float* q0p = qp + (size_t)(w * 16 + lr) * HD;
        const float* q1p = q0p + 8 * HD;
        #pragma unroll
        for (int ks = 0; ks < 4; ks++) {
            const int k = ks * 16 + 2 * lc;
            float2 t0 = *(const float2*)&q0p[k];
            float2 t1 = *(const float2*)&q1p[k];
            float2 t2 = *(const float2*)&q0p[k + 8];
            float2 t3 = *(const float2*)&q1p[k + 8];
            qa[ks][0] = ph2(t0.x * sc2, t0.y * sc2);
            qa[ks][1] = ph2(t1.x * sc2, t1.y * sc2);
            qa[ks][2] = ph2(t2.x * sc2, t2.y * sc2);
            qa[ks][3] = ph2(t3.x * sc2, t3.y * sc2);
        }
    }

    #pragma unroll
    for (int q = 0; q < 8; q++) {
        const int p = tid + q * 128;
        float4 t = ((const float4*)(kp))[p];
        rk[q] = make_uint2(ph2(t.x, t.y), ph2(t.z, t.w));
    }
    #pragma unroll
    for (int q = 0; q < 4; q++) {
        const int p  = tid + q * 128;
        const int rp = p & 31, hq = p >> 5;
        float4 va = ((const float4*)(vp + (size_t)(2 * rp) * HD))[hq];
        float4 vb = ((const float4*)(vp + (size_t)(2 * rp + 1) * HD))[hq];
        rv[q][0] = ph2(va.x, vb.x); rv[q][1] = ph2(va.y, vb.y);
        rv[q][2] = ph2(va.z, vb.z); rv[q][3] = ph2(va.w, vb.w);
    }
    #pragma unroll
    for (int q = 0; q < 8; q++) {
        const int p = tid + q * 128;
        const int r = p >> 4, hq = p & 15;
        *(uint2*)&Ks[r * AW + hq * 2] = rk[q];
    }
    #pragma unroll
    for (int q = 0; q < 4; q++) {
        const int p  = tid + q * 128;
        const int rp = p & 31, hq = p >> 5;
        #pragma unroll
        for (int i = 0; i < 4; i++)
            Vp[(hq * 4 + i) * AW + rp] = rv[q][i];
    }
    __syncthreads();

    float m_r[2] = {-1e30f, -1e30f};
    float l_r[2] = {0.f, 0.f};
    float o[8][4];
    #pragma unroll
    for (int nt = 0; nt < 8; nt++)
        #pragma unroll
        for (int r = 0; r < 4; r++) o[nt][r] = 0.f;

    const int ntiles = qt + 1;
    const int row0 = q0 + w * 16 + lr;
    const int row1 = row0 + 8;

    for (int t = 0; t < ntiles; t++) {
        const int cur  = t & 1;
        const bool more = (t + 1 < ntiles);
        uint32* Kc = Ks + cur * 64 * AW;
        uint32* Vc = Vp + cur * 64 * AW;

        if (more) {
            const int k1 = (t + 1) * 64;
            #pragma unroll
            for (int q = 0; q < 8; q++) {
                const int p = tid + q * 128;
                float4 tk = ((const float4*)(kp + (size_t)k1 * HD))[p];
                rk[q] = make_uint2(ph2(tk.x, tk.y), ph2(tk.z, tk.w));
            }
            #pragma unroll
            for (int q = 0; q < 4; q++) {
                const int p  = tid + q * 128;
                const int rp = p & 31, hq = p >> 5;
                float4 va = ((const float4*)(vp + (size_t)(k1 + 2 * rp) * HD))[hq];
                float4 vb = ((const float4*)(vp + (size_t)(k1 + 2 * rp + 1) * HD))[hq];
                rv[q][0] = ph2(va.x, vb.x); rv[q][1] = ph2(va.y, vb.y);
                rv[q][2] = ph2(va.z, vb.z); rv[q][3] = ph2(va.w, vb.w);
            }
        }

        float s[8][4];
        #pragma unroll
        for (int nt = 0; nt < 8; nt++)
            #pragma unroll
            for (int r = 0; r < 4; r++) s[nt][r] = 0.f;

        #pragma unroll
        for (int ks = 0; ks < 4; ks++) {
            const int kb = ks * 8;
            #pragma unroll
            for (int nt = 0; nt < 8; nt++) {
                const int nb = nt * 8 + lr;
                const uint32 b0 = Kc[nb * AW + kb + lc];
                const uint32 b1 = Kc[nb * AW + kb + lc + 4];
                mma_f16(s[nt], qa[ks][0], qa[ks][1], qa[ks][2], qa[ks][3], b0, b1);
            }
        }

        if (t == qt) {
            #pragma unroll
            for (int nt = 0; nt < 8; nt++) {
                const int col = q0 + nt * 8 + 2 * lc;
                #pragma unroll
                for (int r = 0; r < 4; r++) {
                    const int gr = (r < 2) ? row0 : row1;
                    const int gc = col + (r & 1);
                    if (gc > gr) s[nt][r] = -1e30f;
                }
            }
        }

        float alpha[2];
        #pragma unroll
        for (int h = 0; h < 2; h++) {
            float rm = -1e30f;
            #pragma unroll
            for (int nt = 0; nt < 8; nt++)
                rm = fmaxf(rm, fmaxf(s[nt][2 * h], s[nt][2 * h + 1]));
            rm = fmaxf(rm, __shfl_xor_sync(0xffffffffu, rm, 1));
            rm = fmaxf(rm, __shfl_xor_sync(0xffffffffu, rm, 2));
            const float mnew = fmaxf(m_r[h], rm);
            alpha[h] = exp2f(m_r[h] - mnew);
            m_r[h] = mnew;

            float rs = 0.f;
            #pragma unroll
            for (int nt = 0; nt < 8; nt++) {
                const float p0 = exp2f(s[nt][2 * h]     - mnew);
                const float p1 = exp2f(s[nt][2 * h + 1] - mnew);
                s[nt][2 * h] = p0; s[nt][2 * h + 1] = p1;
                rs += p0 + p1;
            }
            rs += __shfl_xor_sync(0xffffffffu, rs, 1);
            rs += __shfl_xor_sync(0xffffffffu, rs, 2);
            l_r[h] = l_r[h] * alpha[h] + rs;
        }

        if (__any_sync(0xffffffffu, (alpha[0] < 1.0f) | (alpha[1] < 1.0f))) {
            #pragma unroll
            for (int nt = 0; nt < 8; nt++) {
                o[nt][0] *= alpha[0]; o[nt][1] *= alpha[0];
                o[nt][2] *= alpha[1]; o[nt][3] *= alpha[1];
            }
        }

        uint32 pA[8][2];
        #pragma unroll
        for (int nt = 0; nt < 8; nt++) {
            pA[nt][0] = ph2(s[nt][0], s[nt][1]);
            pA[nt][1] = ph2(s[nt][2], s[nt][3]);
        }

        #pragma unroll
        for (int ks = 0; ks < 4; ks++) {
            const int kb = ks * 8;
            const uint32 a0 = pA[2 * ks][0];
            const uint32 a1 = pA[2 * ks][1];
            const uint32 a2 = pA[2 * ks + 1][0];
            const uint32 a3 = pA[2 * ks + 1][1];
            #pragma unroll
            for (int nt = 0; nt < 8; nt++) {
                const int nb = nt * 8 + lr;
                const uint32 b0 = Vc[nb * AW + kb + lc];
                const uint32 b1 = Vc[nb * AW + kb + lc + 4];
                mma_f16(o[nt], a0, a1, a2, a3, b0, b1);
            }
        }

        if (more) {
            const int nxt = cur ^ 1;
            uint32* Kn = Ks + nxt * 64 * AW;
            uint32* Vn = Vp + nxt * 64 * AW;
            #pragma unroll
            for (int q = 0; q < 8; q++) {
                const int p = tid + q * 128;
                const int r = p >> 4, hq = p & 15;
                *(uint2*)&Kn[r * AW + hq * 2] = rk[q];
            }
            #pragma unroll
            for (int q = 0; q < 4; q++) {
                const int p  = tid + q * 128;
                const int rp = p & 31, hq = p >> 5;
                #pragma unroll
                for (int i = 0; i < 4; i++)
                    Vn[(hq * 4 + i) * AW + rp] = rv[q][i];
            }
            __syncthreads();
        }
    }

    const float il0 = 1.0f / l_r[0];
    const float il1 = 1.0f / l_r[1];
    #pragma unroll
    for (int nt = 0; nt < 8; nt++) {
        const int d0 = nt * 8 + 2 * lc;
        *(ull*)&out[((size_t)b * SEQ + row0) * HD + d0] = pk2(o[nt][0] * il0, o[nt][1] * il0);
        *(ull*)&out[((size_t)b * SEQ + row1) * HD + d0] = pk2(o[nt][2] * il1, o[nt][3] * il1);
    }
}

extern "C" void kernel_launch(void* const* d_in, const int* in_sizes, int n_in,
                              void* d_out, int out_size)
{
    const float* x  = (const float*)d_in[0];
    const float* Wq = (const float*)d_in[1];
    const float* Wk = (const float*)d_in[2];
    const float* Wv = (const float*)d_in[3];
    float* out = (float*)d_out;

    rope_table_kernel<<<(SEQ * 32 + 255) / 256, 256>>>();

    cudaFuncSetAttribute(qkv_kernel, cudaFuncAttributeMaxDynamicSharedMemorySize, QKV_SMEM);
    dim3 g1(3, (BSZ * SEQ) / 128);
    qkv_kernel<<<g1, 256, QKV_SMEM>>>(x, Wq, Wk, Wv);

    const int smem = (2 * 64 * AW + 2 * 64 * AW) * (int)sizeof(uint32); // 36864 B
    cudaFuncSetAttribute(attn_kernel, cudaFuncAttributeMaxDynamicSharedMemorySize, smem);
    dim3 g2(SEQ / 64, BSZ);
    attn_kernel<<<g2, 128, smem>>>(out);
}

// round 13
// speedup vs baseline: 1.4929x; 1.4929x over previous
#include <cuda_runtime.h>
#include <cuda_fp16.h>
#include <math.h>

#define BSZ 32
#define SEQ 1024
#define EMB 768
#define HD  64

typedef unsigned long long ull;
typedef unsigned int uint32;

__device__ __forceinline__ ull pk2(float lo, float hi) {
    ull r; asm("mov.b64 %0, {%1, %2};" : "=l"(r) : "f"(lo), "f"(hi)); return r;
}
__device__ __forceinline__ uint32 ph2(float lo, float hi) {
    uint32 r; asm("cvt.rn.f16x2.f32 %0, %1, %2;" : "=r"(r) : "f"(hi), "f"(lo)); return r;
}
__device__ __forceinline__ void mma_f16(float c[4],
    uint32 a0, uint32 a1, uint32 a2, uint32 a3, uint32 b0, uint32 b1)
{
    asm volatile(
        "mma.sync.aligned.m16n8k16.row.col.f32.f16.f16.f32 "
        "{%0,%1,%2,%3}, {%4,%5,%6,%7}, {%8,%9}, {%0,%1,%2,%3};"
        : "+f"(c[0]), "+f"(c[1]), "+f"(c[2]), "+f"(c[3])
        : "r"(a0), "r"(a1), "r"(a2), "r"(a3), "r"(b0), "r"(b1));
}

__device__ float g_q[BSZ * SEQ * HD];
__device__ float g_k[BSZ * SEQ * HD];
__device__ float g_v[BSZ * SEQ * HD];
__device__ float g_cos[SEQ * 32];
__device__ float g_sin[SEQ * 32];
__device__ int   g_done[BSZ];

// ---------------------------------------------------------------------------
// Kernel 0: RoPE cos/sin table + zero dependency counters
// ---------------------------------------------------------------------------
__global__ void rope_table_kernel()
{
    const int t = blockIdx.x * blockDim.x + threadIdx.x;
    if (t < BSZ) g_done[t] = 0;
    if (t >= SEQ * 32) return;
    const int pos = t >> 5;
    const int pr  = t & 31;
    const float theta = expf((float)pr * -0.5756462732485114f);
    float sn, cs;
    sincosf((float)pos * theta, &sn, &cs);
    g_cos[t] = cs;
    g_sin[t] = sn;
}

// ---------------------------------------------------------------------------
// FUSED kernel: blocks [0,768) = QKV projection (fp16 HMMA + RoPE, R8 path);
//               blocks [768,1024) = causal flash attention (R10 256-thr path),
//               gated per batch on g_done[b] == 24 (8 m-tiles x 3 mats).
// ---------------------------------------------------------------------------
#define XW 20          // qkv smem words/row
#define AW 36          // attn smem words/row
#define NQKV 768
// smem: qkv 30720 B; attn (128+128+128)*36*4 = 55296 B
#define FUSED_SMEM 55296

__global__ __launch_bounds__(256) void fused_kernel(
    const float* __restrict__ x,
    const float* __restrict__ Wq,
    const float* __restrict__ Wk,
    const float* __restrict__ Wv,
    float* __restrict__ out)
{
    extern __shared__ char dynsm[];
    const int bid = blockIdx.x;
    const int tid = threadIdx.x;

    if (bid < NQKV) {
        // ==================== QKV path (R8, proven) ====================
        const int which = bid % 3;
        const int by    = bid / 3;
        const float* __restrict__ W = (which == 0) ? Wq : ((which == 1) ? Wk : Wv);
        float* __restrict__ outp    = (which == 0) ? g_q : ((which == 1) ? g_k : g_v);
        const int m0 = by * 128;

        uint32* xs = (uint32*)dynsm;          // [2][128*XW]
        uint32* ws = xs + 2 * 128 * XW;       // [2][64*XW]

        const int lane   = tid & 31;
        const int wid    = tid >> 5;
        const int warp_m = wid & 3;
        const int warp_n = wid >> 2;
        const int lr = lane >> 2;
        const int lc = lane & 3;

        const int xrow = tid >> 3;
        const int xkq  = tid & 7;

        uint2 rx[4], rw[2];

        float c[2][4][4];
        #pragma unroll
        for (int mt = 0; mt < 2; mt++)
            #pragma unroll
            for (int nt = 0; nt < 4; nt++)
                #pragma unroll
                for (int r = 0; r < 4; r++) c[mt][nt][r] = 0.f;

        #pragma unroll
        for (int q = 0; q < 4; q++) {
            float4 t = *(const float4*)&x[(size_t)(m0 + xrow + q * 32) * EMB + xkq * 4];
            rx[q] = make_uint2(ph2(t.x, t.y), ph2(t.z, t.w));
        }
        #pragma unroll
        for (int q = 0; q < 2; q++) {
            float4 t = *(const float4*)&W[(size_t)(xrow + q * 32) * EMB + xkq * 4];
            rw[q] = make_uint2(ph2(t.x, t.y), ph2(t.z, t.w));
        }
        #pragma unroll
        for (int q = 0; q < 4; q++)
            *(uint2*)&xs[(xrow + q * 32) * XW + xkq * 2] = rx[q];
        #pragma unroll
        for (int q = 0; q < 2; q++)
            *(uint2*)&ws[(xrow + q * 32) * XW + xkq * 2] = rw[q];
        __syncthreads();

        const int NCH = EMB / 32;   // 24
        for (int ec = 0; ec < NCH; ec++) {
            const int cur = ec & 1;
            const bool more = (ec + 1 < NCH);
            if (more) {
                const int e1 = (ec + 1) * 32;
                #pragma unroll
                for (int q = 0; q < 4; q++) {
                    float4 t = *(const float4*)&x[(size_t)(m0 + xrow + q * 32) * EMB + e1 + xkq * 4];
                    rx[q] = make_uint2(ph2(t.x, t.y), ph2(t.z, t.w));
                }
                #pragma unroll
                for (int q = 0; q < 2; q++) {
                    float4 t = *(const float4*)&W[(size_t)(xrow + q * 32) * EMB + e1 + xkq * 4];
                    rw[q] = make_uint2(ph2(t.x, t.y), ph2(t.z, t.w));
                }
            }

            uint32* xc = xs + cur * 128 * XW;
            uint32* wc = ws + cur * 64 * XW;
            #pragma unroll
            for (int ks = 0; ks < 2; ks++) {
                const int kb = ks * 8;
                uint32 a[2][4];
                #pragma unroll
                for (int mt = 0; mt < 2; mt++) {
                    const int rb = warp_m * 32 + mt * 16 + lr;
                    a[mt][0] = xc[rb * XW + kb + lc];
                    a[mt][1] = xc[(rb + 8) * XW + kb + lc];
                    a[mt][2] = xc[rb * XW + kb + lc + 4];
                    a[mt][3] = xc[(rb + 8) * XW + kb + lc + 4];
                }
                uint32 bb[4][2];
                #pragma unroll
                for (int nt = 0; nt < 4; nt++) {
                    const int nb = warp_n * 32 + nt * 8 + lr;
                    bb[nt][0] = wc[nb * XW + kb + lc];
                    bb[nt][1] = wc[nb * XW + kb + lc + 4];
                }
                #pragma unroll
                for (int mt = 0; mt < 2; mt++)
                    #pragma unroll
                    for (int nt = 0; nt < 4; nt++)
                        mma_f16(c[mt][nt], a[mt][0], a[mt][1], a[mt][2], a[mt][3],
                                bb[nt][0], bb[nt][1]);
            }

            if (more) {
                const int nxt = cur ^ 1;
                uint32* xn = xs + nxt * 128 * XW;
                uint32* wn = ws + nxt * 64 * XW;
                #pragma unroll
                for (int q = 0; q < 4; q++)
                    *(uint2*)&xn[(xrow + q * 32) * XW + xkq * 2] = rx[q];
                #pragma unroll
                for (int q = 0; q < 2; q++)
                    *(uint2*)&wn[(xrow + q * 32) * XW + xkq * 2] = rw[q];
                __syncthreads();
            }
        }

        if (which < 2) {
            #pragma unroll
            for (int mt = 0; mt < 2; mt++) {
                const int r0 = m0 + warp_m * 32 + mt * 16 + lr;
                const int r1 = r0 + 8;
                const int p0 = r0 & (SEQ - 1);
                const int p1 = r1 & (SEQ - 1);
                #pragma unroll
                for (int nt = 0; nt < 4; nt++) {
                    const int d0   = warp_n * 32 + nt * 8 + 2 * lc;
                    const int pair = d0 >> 1;
                    {
                        const float cs = g_cos[p0 * 32 + pair];
                        const float sn = g_sin[p0 * 32 + pair];
                        const float av = c[mt][nt][0], bv = c[mt][nt][1];
                        *(ull*)&outp[(size_t)r0 * HD + d0] = pk2(av * cs - bv * sn, bv * cs + av * sn);
                    }
                    {
                        const float cs = g_cos[p1 * 32 + pair];
                        const float sn = g_sin[p1 * 32 + pair];
                        const float av = c[mt][nt][2], bv = c[mt][nt][3];
                        *(ull*)&outp[(size_t)r1 * HD + d0] = pk2(av * cs - bv * sn, bv * cs + av * sn);
                    }
                }
            }
        } else {
            #pragma unroll
            for (int mt = 0; mt < 2; mt++) {
                const int r0 = m0 + warp_m * 32 + mt * 16 + lr;
                #pragma unroll
                for (int nt = 0; nt < 4; nt++) {
                    const int d0 = warp_n * 32 + nt * 8 + 2 * lc;
                    *(ull*)&outp[(size_t)r0 * HD + d0]       = pk2(c[mt][nt][0], c[mt][nt][1]);
                    *(ull*)&outp[(size_t)(r0 + 8) * HD + d0] = pk2(c[mt][nt][2], c[mt][nt][3]);
                }
            }
        }

        // signal: this batch got one more of its 24 producer blocks
        __threadfence();
        __syncthreads();
        if (tid == 0) atomicAdd(&g_done[by >> 3], 1);
    } else {
        // ==================== attention path (R10, proven) ====================
        const int idx = bid - NQKV;          // 0..255
        const int b   = idx >> 3;            // batch
        const int qt  = 7 - (idx & 7);       // largest q-tile first
        const int q0  = qt * 128;

        // wait for this batch's q/k/v (24 producer blocks)
        if (tid == 0) {
            int v;
            do {
                asm volatile("ld.acquire.gpu.b32 %0, [%1];"
                             : "=r"(v) : "l"(&g_done[b]) : "memory");
                if (v < 24) __nanosleep(128);
            } while (v < 24);
        }
        __syncthreads();

        uint32* Ps = (uint32*)dynsm;          // [128 q][36w]
        uint32* Ks = Ps + 128 * AW;           // [2][64 kv][36w]
        uint32* Vp = Ks + 2 * 64 * AW;        // [2][64 h][36w]

        const float* __restrict__ qp = g_q + ((size_t)b * SEQ + q0) * HD;
        const float* __restrict__ kp = g_k + (size_t)b * SEQ * HD;
        const float* __restrict__ vp = g_v + (size_t)b * SEQ * HD;

        const int lane = tid & 31;
        const int w    = tid >> 5;
        const int lr   = lane >> 2;
        const int lc   = lane & 3;

        uint2  rk[4];
        uint32 rv[2][4];

        const float sc2 = 0.03608439182435161f * 1.4426950408889634f;

        uint32 qa[4][4];
        {
            const float* q0p = qp + (size_t)(w * 16 + lr) * HD;
            const float* q1p = q0p + 8 * HD;
            #pragma unroll
            for (int ks = 0; ks < 4; ks++) {
                const int k = ks * 16 + 2 * lc;
                float2 t0 = *(const float2*)&q0p[k];
                float2 t1 = *(const float2*)&q1p[k];
                float2 t2 = *(const float2*)&q0p[k + 8];
                float2 t3 = *(const float2*)&q1p[k + 8];
                qa[ks][0] = ph2(t0.x * sc2, t0.y * sc2);
                qa[ks][1] = ph2(t1.x * sc2, t1.y * sc2);
                qa[ks][2] = ph2(t2.x * sc2, t2.y * sc2);
                qa[ks][3] = ph2(t3.x * sc2, t3.y * sc2);
            }
        }

        #pragma unroll
        for (int q = 0; q < 4; q++) {
            const int p = tid + q * 256;
            float4 t = ((const float4*)(kp))[p];
            rk[q] = make_uint2(ph2(t.x, t.y), ph2(t.z, t.w));
        }
        #pragma unroll
        for (int q = 0; q < 2; q++) {
            const int p  = tid + q * 256;
            const int rp = p & 31, hq = p >> 5;
            float4 va = ((const float4*)(vp + (size_t)(2 * rp) * HD))[hq];
            float4 vb = ((const float4*)(vp + (size_t)(2 * rp + 1) * HD))[hq];
            rv[q][0] = ph2(va.x, vb.x); rv[q][1] = ph2(va.y, vb.y);
            rv[q][2] = ph2(va.z, vb.z); rv[q][3] = ph2(va.w, vb.w);
        }
        #pragma unroll
        for (int q = 0; q < 4; q++) {
            const int p = tid + q * 256;
            const int r = p >> 4, hq = p & 15;
            *(uint2*)&Ks[r * AW + hq * 2] = rk[q];
        }
        #pragma unroll
        for (int q = 0; q < 2; q++) {
            const int p  = tid + q * 256;
            const int rp = p & 31, hq = p >> 5;
            #pragma unroll
            for (int i = 0; i < 4; i++)
                Vp[(hq * 4 + i) * AW + rp] = rv[q][i];
        }
        __syncthreads();

        float m_r[2] = {-1e30f, -1e30f};
        float l_r[2] = {0.f, 0.f};
        float o[8][4];
        #pragma unroll
        for (int nt = 0; nt < 8; nt++)
            #pragma unroll
            for (int r = 0; r < 4; r++) o[nt][r] = 0.f;

        const int ntiles = 2 * qt + 2;
        const int row0 = q0 + w * 16 + lr;
        const int row1 = row0 + 8;

        for (int t = 0; t < ntiles; t++) {
            const int cur  = t & 1;
            const bool more = (t + 1 < ntiles);
            uint32* Kc = Ks + cur * 64 * AW;
            uint32* Vc = Vp + cur * 64 * AW;

            if (more) {
                const int k1 = (t + 1) * 64;
                #pragma unroll
                for (int q = 0; q < 4; q++) {
                    const int p = tid + q * 256;
                    float4 tk = ((const float4*)(kp + (size_t)k1 * HD))[p];
                    rk[q] = make_uint2(ph2(tk.x, tk.y), ph2(tk.z, tk.w));
                }
                #pragma unroll
                for (int q = 0; q < 2; q++) {
                    const int p  = tid + q * 256;
                    const int rp = p & 31, hq = p >> 5;
                    float4 va = ((const float4*)(vp + (size_t)(k1 + 2 * rp) * HD))[hq];
                    float4 vb = ((const float4*)(vp + (size_t)(k1 + 2 * rp + 1) * HD))[hq];
                    rv[q][0] = ph2(va.x, vb.x); rv[q][1] = ph2(va.y, vb.y);
                    rv[q][2] = ph2(va.z, vb.z); rv[q][3] = ph2(va.w, vb.w);
                }
            }

            float s[8][4];
            #pragma unroll
            for (int nt = 0; nt < 8; nt++)
                #pragma unroll
                for (int r = 0; r < 4; r++) s[nt][r] = 0.f;

            #pragma unroll
            for (int ks = 0; ks < 4; ks++) {
                const int kb = ks * 8;
                #pragma unroll
                for (int nt = 0; nt < 8; nt++) {
                    const int nb = nt * 8 + lr;
                    const uint32 b0 = Kc[nb * AW + kb + lc];
                    const uint32 b1 = Kc[nb * AW + kb + lc + 4];
                    mma_f16(s[nt], qa[ks][0], qa[ks][1], qa[ks][2], qa[ks][3], b0, b1);
                }
            }

            if (t * 64 + 63 > row0) {
                #pragma unroll
                for (int nt = 0; nt < 8; nt++) {
                    const int col = t * 64 + nt * 8 + 2 * lc;
                    #pragma unroll
                    for (int r = 0; r < 4; r++) {
                        const int gr = (r < 2) ? row0 : row1;
                        const int gc = col + (r & 1);
                        if (gc > gr) s[nt][r] = -1e30f;
                    }
                }
            }

            float alpha[2];
            #pragma unroll
            for (int h = 0; h < 2; h++) {
                float rm = -1e30f;
                #pragma unroll
                for (int nt = 0; nt < 8; nt++)
                    rm = fmaxf(rm, fmaxf(s[nt][2 * h], s[nt][2 * h + 1]));
                rm = fmaxf(rm, __shfl_xor_sync(0xffffffffu, rm, 1));
                rm = fmaxf(rm, __shfl_xor_sync(0xffffffffu, rm, 2));
                const float mnew = fmaxf(m_r[h], rm);
                alpha[h] = exp2f(m_r[h] - mnew);
                m_r[h] = mnew;

                float rs = 0.f;
                #pragma unroll
                for (int nt = 0; nt < 8; nt++) {
                    const float p0 = exp2f(s[nt][2 * h]     - mnew);
                    const float p1 = exp2f(s[nt][2 * h + 1] - mnew);
                    s[nt][2 * h] = p0; s[nt][2 * h + 1] = p1;
                    rs += p0 + p1;
                }
                rs += __shfl_xor_sync(0xffffffffu, rs, 1);
                rs += __shfl_xor_sync(0xffffffffu, rs, 2);
                l_r[h] = l_r[h] * alpha[h] + rs;
            }

            if (__any_sync(0xffffffffu, (alpha[0] < 1.0f) | (alpha[1] < 1.0f))) {
                #pragma unroll
                for (int nt = 0; nt < 8; nt++) {
                    o[nt][0] *= alpha[0]; o[nt][1] *= alpha[0];
                    o[nt][2] *= alpha[1]; o[nt][3] *= alpha[1];
                }
            }

            uint32 pA[8][2];
            #pragma unroll
            for (int nt = 0; nt < 8; nt++) {
                pA[nt][0] = ph2(s[nt][0], s[nt][1]);
                pA[nt][1] = ph2(s[nt][2], s[nt][3]);
            }

            #pragma unroll
            for (int ks = 0; ks < 4; ks++) {
                const int kb = ks * 8;
                const uint32 a0 = pA[2 * ks][0];
                const uint32 a1 = pA[2 * ks][1];
                const uint32 a2 = pA[2 * ks + 1][0];
                const uint32 a3 = pA[2 * ks + 1][1];
                #pragma unroll
                for (int nt = 0; nt < 8; nt++) {
                    const int nb = nt * 8 + lr;
                    const uint32 b0 = Vc[nb * AW + kb + lc];
                    const uint32 b1 = Vc[nb * AW + kb + lc + 4];
                    mma_f16(o[nt], a0, a1, a2, a3, b0, b1);
                }
            }

            if (more) {
                const int nxt = cur ^ 1;
                uint32* Kn = Ks + nxt * 64 * AW;
                uint32* Vn = Vp + nxt * 64 * AW;
                #pragma unroll
                for (int q = 0; q < 4; q++) {
                    const int p = tid + q * 256;
                    const int r = p >> 4, hq = p & 15;
                    *(uint2*)&Kn[r * AW + hq * 2] = rk[q];
                }
                #pragma unroll
                for (int q = 0; q < 2; q++) {
                    const int p  = tid + q * 256;
                    const int rp = p & 31, hq = p >> 5;
                    #pragma unroll
                    for (int i = 0; i < 4; i++)
                        Vn[(hq * 4 + i) * AW + rp] = rv[q][i];
                }
                __syncthreads();
            }
        }

        const float il0 = 1.0f / l_r[0];
        const float il1 = 1.0f / l_r[1];
        #pragma unroll
        for (int nt = 0; nt < 8; nt++) {
            const int d0 = nt * 8 + 2 * lc;
            *(ull*)&out[((size_t)b * SEQ + row0) * HD + d0] = pk2(o[nt][0] * il0, o[nt][1] * il0);
            *(ull*)&out[((size_t)b * SEQ + row1) * HD + d0] = pk2(o[nt][2] * il1, o[nt][3] * il1);
        }
    }
}

extern "C" void kernel_launch(void* const* d_in, const int* in_sizes, int n_in,
                              void* d_out, int out_size)
{
    const float* x  = (const float*)d_in[0];
    const float* Wq = (const float*)d_in[1];
    const float* Wk = (const float*)d_in[2];
    const float* Wv = (const float*)d_in[3];
    float* out = (float*)d_out;

    rope_table_kernel<<<(SEQ * 32 + 255) / 256, 256>>>();

    cudaFuncSetAttribute(fused_kernel, cudaFuncAttributeMaxDynamicSharedMemorySize, FUSED_SMEM);
    fused_kernel<<<NQKV + 256, 256, FUSED_SMEM>>>(x, Wq, Wk, Wv, out);
}

// round 14
// speedup vs baseline: 1.9517x; 1.3074x over previous
#include <cuda_runtime.h>
#include <cuda_fp16.h>
#include <math.h>

#define BSZ 32
#define SEQ 1024
#define EMB 768
#define HD  64

typedef unsigned long long ull;
typedef unsigned int uint32;

__device__ __forceinline__ ull pk2(float lo, float hi) {
    ull r; asm("mov.b64 %0, {%1, %2};" : "=l"(r) : "f"(lo), "f"(hi)); return r;
}
__device__ __forceinline__ uint32 ph2(float lo, float hi) {
    uint32 r; asm("cvt.rn.f16x2.f32 %0, %1, %2;" : "=r"(r) : "f"(hi), "f"(lo)); return r;
}
__device__ __forceinline__ void mma_f16(float c[4],
    uint32 a0, uint32 a1, uint32 a2, uint32 a3, uint32 b0, uint32 b1)
{
    asm volatile(
        "mma.sync.aligned.m16n8k16.row.col.f32.f16.f16.f32 "
        "{%0,%1,%2,%3}, {%4,%5,%6,%7}, {%8,%9}, {%0,%1,%2,%3};"
        : "+f"(c[0]), "+f"(c[1]), "+f"(c[2]), "+f"(c[3])
        : "r"(a0), "r"(a1), "r"(a2), "r"(a3), "r"(b0), "r"(b1));
}
__device__ __forceinline__ uint32 smem_u32(const void* p) {
    uint32 a;
    asm("{ .reg .u64 t; cvta.to.shared.u64 t, %1; cvt.u32.u64 %0, t; }" : "=r"(a) : "l"(p));
    return a;
}
#define CP_ASYNC16(dst, src) \
    asm volatile("cp.async.ca.shared.global [%0], [%1], 16;" :: "r"(dst), "l"(src))
#define CP_COMMIT() asm volatile("cp.async.commit_group;" ::: "memory")
#define CP_WAIT(N)  asm volatile("cp.async.wait_group %0;" :: "n"(N) : "memory")

// fp16 intermediates (q pre-scaled by scale*log2e; v stored transposed [b][h][kv])
__device__ __half g_qh[BSZ * SEQ * HD];
__device__ __half g_kh[BSZ * SEQ * HD];
__device__ __half g_vt[BSZ * HD * SEQ];
__device__ float  g_cos[SEQ * 32];
__device__ float  g_sin[SEQ * 32];

// ---------------------------------------------------------------------------
// Kernel 0: RoPE cos/sin table
// ---------------------------------------------------------------------------
__global__ void rope_table_kernel()
{
    const int t = blockIdx.x * blockDim.x + threadIdx.x;
    if (t >= SEQ * 32) return;
    const int pos = t >> 5;
    const int pr  = t & 31;
    const float theta = expf((float)pr * -0.5756462732485114f);
    float sn, cs;
    sincosf((float)pos * theta, &sn, &cs);
    g_cos[t] = cs;
    g_sin[t] = sn;
}

// ---------------------------------------------------------------------------
// Kernel 1: QKV projection (fp16 HMMA, R8 core) + RoPE; fp16 outputs.
//   grid = (3, 256), 256 thr.
// ---------------------------------------------------------------------------
#define XW 20

__global__ __launch_bounds__(256) void qkv_rope_kernel(
    const float* __restrict__ x,
    const float* __restrict__ Wq,
    const float* __restrict__ Wk,
    const float* __restrict__ Wv)
{
    const int which = blockIdx.x;
    const float* __restrict__ W = (which == 0) ? Wq : ((which == 1) ? Wk : Wv);

    const int m0 = blockIdx.y * 128;

    __shared__ uint32 xs[2][128 * XW];
    __shared__ uint32 ws[2][64 * XW];

    const int tid    = threadIdx.x;
    const int lane   = tid & 31;
    const int wid    = tid >> 5;
    const int warp_m = wid & 3;
    const int warp_n = wid >> 2;
    const int lr = lane >> 2;
    const int lc = lane & 3;

    const int xrow = tid >> 3;
    const int xkq  = tid & 7;

    uint2 rx[4], rw[2];

    float c[2][4][4];
    #pragma unroll
    for (int mt = 0; mt < 2; mt++)
        #pragma unroll
        for (int nt = 0; nt < 4; nt++)
            #pragma unroll
            for (int r = 0; r < 4; r++) c[mt][nt][r] = 0.f;

    #pragma unroll
    for (int q = 0; q < 4; q++) {
        float4 t = *(const float4*)&x[(size_t)(m0 + xrow + q * 32) * EMB + xkq * 4];
        rx[q] = make_uint2(ph2(t.x, t.y), ph2(t.z, t.w));
    }
    #pragma unroll
    for (int q = 0; q < 2; q++) {
        float4 t = *(const float4*)&W[(size_t)(xrow + q * 32) * EMB + xkq * 4];
        rw[q] = make_uint2(ph2(t.x, t.y), ph2(t.z, t.w));
    }
    #pragma unroll
    for (int q = 0; q < 4; q++)
        *(uint2*)&xs[0][(xrow + q * 32) * XW + xkq * 2] = rx[q];
    #pragma unroll
    for (int q = 0; q < 2; q++)
        *(uint2*)&ws[0][(xrow + q * 32) * XW + xkq * 2] = rw[q];
    __syncthreads();

    const int NCH = EMB / 32;   // 24
    for (int ec = 0; ec < NCH; ec++) {
        const int cur = ec & 1;
        const bool more = (ec + 1 < NCH);
        if (more) {
            const int e1 = (ec + 1) * 32;
            #pragma unroll
            for (int q = 0; q < 4; q++) {
                float4 t = *(const float4*)&x[(size_t)(m0 + xrow + q * 32) * EMB + e1 + xkq * 4];
                rx[q] = make_uint2(ph2(t.x, t.y), ph2(t.z, t.w));
            }
            #pragma unroll
            for (int q = 0; q < 2; q++) {
                float4 t = *(const float4*)&W[(size_t)(xrow + q * 32) * EMB + e1 + xkq * 4];
                rw[q] = make_uint2(ph2(t.x, t.y), ph2(t.z, t.w));
            }
        }

        #pragma unroll
        for (int ks = 0; ks < 2; ks++) {
            const int kb = ks * 8;
            uint32 a[2][4];
            #pragma unroll
            for (int mt = 0; mt < 2; mt++) {
                const int rb = warp_m * 32 + mt * 16 + lr;
                a[mt][0] = xs[cur][rb * XW + kb + lc];
                a[mt][1] = xs[cur][(rb + 8) * XW + kb + lc];
                a[mt][2] = xs[cur][rb * XW + kb + lc + 4];
                a[mt][3] = xs[cur][(rb + 8) * XW + kb + lc + 4];
            }
            uint32 bb[4][2];
            #pragma unroll
            for (int nt = 0; nt < 4; nt++) {
                const int nb = warp_n * 32 + nt * 8 + lr;
                bb[nt][0] = ws[cur][nb * XW + kb + lc];
                bb[nt][1] = ws[cur][nb * XW + kb + lc + 4];
            }
            #pragma unroll
            for (int mt = 0; mt < 2; mt++)
                #pragma unroll
                for (int nt = 0; nt < 4; nt++)
                    mma_f16(c[mt][nt], a[mt][0], a[mt][1], a[mt][2], a[mt][3],
                            bb[nt][0], bb[nt][1]);
        }

        if (more) {
            const int nxt = cur ^ 1;
            #pragma unroll
            for (int q = 0; q < 4; q++)
                *(uint2*)&xs[nxt][(xrow + q * 32) * XW + xkq * 2] = rx[q];
            #pragma unroll
            for (int q = 0; q < 2; q++)
                *(uint2*)&ws[nxt][(xrow + q * 32) * XW + xkq * 2] = rw[q];
            __syncthreads();
        }
    }

    if (which < 2) {
        // RoPE; q additionally pre-scaled by scale*log2e
        const float sc = (which == 0) ? (0.03608439182435161f * 1.4426950408889634f) : 1.0f;
        __half* outp = (which == 0) ? g_qh : g_kh;
        #pragma unroll
        for (int mt = 0; mt < 2; mt++) {
            const int r0 = m0 + warp_m * 32 + mt * 16 + lr;
            const int r1 = r0 + 8;
            const int p0 = r0 & (SEQ - 1);
            const int p1 = r1 & (SEQ - 1);
            #pragma unroll
            for (int nt = 0; nt < 4; nt++) {
                const int d0   = warp_n * 32 + nt * 8 + 2 * lc;
                const int pair = d0 >> 1;
                {
                    const float cs = g_cos[p0 * 32 + pair];
                    const float sn = g_sin[p0 * 32 + pair];
                    const float av = c[mt][nt][0], bv = c[mt][nt][1];
                    *(uint32*)&outp[(size_t)r0 * HD + d0] =
                        ph2((av * cs - bv * sn) * sc, (bv * cs + av * sn) * sc);
                }
                {
                    const float cs = g_cos[p1 * 32 + pair];
                    const float sn = g_sin[p1 * 32 + pair];
                    const float av = c[mt][nt][2], bv = c[mt][nt][3];
                    *(uint32*)&outp[(size_t)r1 * HD + d0] =
                        ph2((av * cs - bv * sn) * sc, (bv * cs + av * sn) * sc);
                }
            }
        }
    } else {
        // v transposed: g_vt[b][h][kv]
        #pragma unroll
        for (int mt = 0; mt < 2; mt++) {
            const int r0  = m0 + warp_m * 32 + mt * 16 + lr;
            const int b   = r0 >> 10;
            const int kv0 = r0 & (SEQ - 1);
            __half* vb = g_vt + (size_t)b * HD * SEQ;
            #pragma unroll
            for (int nt = 0; nt < 4; nt++) {
                const int d0 = warp_n * 32 + nt * 8 + 2 * lc;
                vb[(size_t)d0 * SEQ + kv0]           = __float2half_rn(c[mt][nt][0]);
                vb[(size_t)(d0 + 1) * SEQ + kv0]     = __float2half_rn(c[mt][nt][1]);
                vb[(size_t)d0 * SEQ + kv0 + 8]       = __float2half_rn(c[mt][nt][2]);
                vb[(size_t)(d0 + 1) * SEQ + kv0 + 8] = __float2half_rn(c[mt][nt][3]);
            }
        }
    }
}

// ---------------------------------------------------------------------------
// Kernel 2: causal flash attention — fp16 inputs, cp.async staged K/V,
//   register P, Q fragments from global. 64-row q tiles, 128 threads.
// ---------------------------------------------------------------------------
#define AW 36    // words per smem row (144 B, 16B-aligned stride)

__global__ __launch_bounds__(128) void attn_kernel(float* __restrict__ out)
{
    extern __shared__ uint32 smu[];
    uint32* Ks = smu;                     // [2][64 kv][36w] fp16 [kv][h]
    uint32* Vp = Ks + 2 * 64 * AW;        // [2][64 h][36w]  fp16 [h][kvpair]
    const uint32 ks_base = smem_u32(Ks);
    const uint32 vp_base = smem_u32(Vp);

    const int b  = blockIdx.y;
    const int qt = (SEQ / 64 - 1) - blockIdx.x;   // largest work first
    const int q0 = qt * 64;

    const __half* __restrict__ qh = g_qh + ((size_t)b * SEQ + q0) * HD;
    const __half* __restrict__ kh = g_kh + (size_t)b * SEQ * HD;
    const __half* __restrict__ vt = g_vt + (size_t)b * HD * SEQ;

    const int tid  = threadIdx.x;
    const int lane = tid & 31;
    const int w    = tid >> 5;
    const int lr   = lane >> 2;
    const int lc   = lane & 3;

    // staging task: p = tid + q*128, q<4 -> row p>>3 (0..63), 16B seg p&7
    const int srow = tid >> 3;
    const int sseg = tid & 7;

    // ---- Q fragments (pre-scaled fp16, direct global loads) ----
    uint32 qa[4][4];
    {
        const __half* q0p = qh + (size_t)(w * 16 + lr) * HD;
        const __half* q1p = q0p + 8 * HD;
        #pragma unroll
        for (int ks = 0; ks < 4; ks++) {
            const int k = ks * 16 + 2 * lc;
            qa[ks][0] = *(const uint32*)&q0p[k];
            qa[ks][1] = *(const uint32*)&q1p[k];
            qa[ks][2] = *(const uint32*)&q0p[k + 8];
            qa[ks][3] = *(const uint32*)&q1p[k + 8];
        }
    }

    const int ntiles = qt + 1;

    // ---- prologue: stage tiles 0 (and 1) via cp.async ----
    {
        #pragma unroll
        for (int q = 0; q < 8; q++) {       // 4 K rows + 4 V rows interleaved
            const int r = srow + (q & 3) * 16;
            if (q < 4) {
                CP_ASYNC16(ks_base + (uint32)(r * 144 + sseg * 16),
                           (const char*)&kh[(size_t)r * HD + sseg * 8]);
            } else {
                CP_ASYNC16(vp_base + (uint32)(r * 144 + sseg * 16),
                           (const char*)&vt[(size_t)r * SEQ + sseg * 8]);
            }
        }
        CP_COMMIT();
        if (ntiles > 1) {
            #pragma unroll
            for (int q = 0; q < 8; q++) {
                const int r = srow + (q & 3) * 16;
                if (q < 4) {
                    CP_ASYNC16(ks_base + (uint32)(64 * 144 + r * 144 + sseg * 16),
                               (const char*)&kh[(size_t)(64 + r) * HD + sseg * 8]);
                } else {
                    CP_ASYNC16(vp_base + (uint32)(64 * 144 + r * 144 + sseg * 16),
                               (const char*)&vt[(size_t)r * SEQ + 64 + sseg * 8]);
                }
            }
            CP_COMMIT();
        }
    }

    float m_r[2] = {-1e30f, -1e30f};
    float l_r[2] = {0.f, 0.f};
    float o[8][4];
    #pragma unroll
    for (int nt = 0; nt < 8; nt++)
        #pragma unroll
        for (int r = 0; r < 4; r++) o[nt][r] = 0.f;

    const int row0 = q0 + w * 16 + lr;
    const int row1 = row0 + 8;

    for (int t = 0; t < ntiles; t++) {
        const int cur = t & 1;
        uint32* Kc = Ks + cur * 64 * AW;
        uint32* Vc = Vp + cur * 64 * AW;

        // wait for tile t (leave at most the t+1 group outstanding)
        if (t + 1 < ntiles) { CP_WAIT(1); } else { CP_WAIT(0); }
        __syncthreads();

        // ---- S = Q K^T (Q pre-scaled: log2 softmax domain) ----
        float s[8][4];
        #pragma unroll
        for (int nt = 0; nt < 8; nt++)
            #pragma unroll
            for (int r = 0; r < 4; r++) s[nt][r] = 0.f;

        #pragma unroll
        for (int ks = 0; ks < 4; ks++) {
            const int kb = ks * 8;
            #pragma unroll
            for (int nt = 0; nt < 8; nt++) {
                const int nb = nt * 8 + lr;
                const uint32 b0 = Kc[nb * AW + kb + lc];
                const uint32 b1 = Kc[nb * AW + kb + lc + 4];
                mma_f16(s[nt], qa[ks][0], qa[ks][1], qa[ks][2], qa[ks][3], b0, b1);
            }
        }

        // causal mask (diagonal tile only)
        if (t == qt) {
            #pragma unroll
            for (int nt = 0; nt < 8; nt++) {
                const int col = q0 + nt * 8 + 2 * lc;
                #pragma unroll
                for (int r = 0; r < 4; r++) {
                    const int gr = (r < 2) ? row0 : row1;
                    const int gc = col + (r & 1);
                    if (gc > gr) s[nt][r] = -1e30f;
                }
            }
        }

        // ---- online softmax ----
        float alpha[2];
        #pragma unroll
        for (int h = 0; h < 2; h++) {
            float rm = -1e30f;
            #pragma unroll
            for (int nt = 0; nt < 8; nt++)
                rm = fmaxf(rm, fmaxf(s[nt][2 * h], s[nt][2 * h + 1]));
            rm = fmaxf(rm, __shfl_xor_sync(0xffffffffu, rm, 1));
            rm = fmaxf(rm, __shfl_xor_sync(0xffffffffu, rm, 2));
            const float mnew = fmaxf(m_r[h], rm);
            alpha[h] = exp2f(m_r[h] - mnew);
            m_r[h] = mnew;

            float rs = 0.f;
            #pragma unroll
            for (int nt = 0; nt < 8; nt++) {
                const float p0 = exp2f(s[nt][2 * h]     - mnew);
                const float p1 = exp2f(s[nt][2 * h + 1] - mnew);
                s[nt][2 * h] = p0; s[nt][2 * h + 1] = p1;
                rs += p0 + p1;
            }
            rs += __shfl_xor_sync(0xffffffffu, rs, 1);
            rs += __shfl_xor_sync(0xffffffffu, rs, 2);
            l_r[h] = l_r[h] * alpha[h] + rs;
        }

        if (__any_sync(0xffffffffu, (alpha[0] < 1.0f) | (alpha[1] < 1.0f))) {
            #pragma unroll
            for (int nt = 0; nt < 8; nt++) {
                o[nt][0] *= alpha[0]; o[nt][1] *= alpha[0];
                o[nt][2] *= alpha[1]; o[nt][3] *= alpha[1];
            }
        }

        // ---- P fragments in registers ----
        uint32 pA[8][2];
        #pragma unroll
        for (int nt = 0; nt < 8; nt++) {
            pA[nt][0] = ph2(s[nt][0], s[nt][1]);
            pA[nt][1] = ph2(s[nt][2], s[nt][3]);
        }

        // ---- O += P V ----
        #pragma unroll
        for (int ks = 0; ks < 4; ks++) {
            const int kb = ks * 8;
            const uint32 a0 = pA[2 * ks][0];
            const uint32 a1 = pA[2 * ks][1];
            const uint32 a2 = pA[2 * ks + 1][0];
            const uint32 a3 = pA[2 * ks + 1][1];
            #pragma unroll
            for (int nt = 0; nt < 8; nt++) {
                const int nb = nt * 8 + lr;
                const uint32 b0 = Vc[nb * AW + kb + lc];
                const uint32 b1 = Vc[nb * AW + kb + lc + 4];
                mma_f16(o[nt], a0, a1, a2, a3, b0, b1);
            }
        }

        __syncthreads();   // all reads of buffer `cur` complete before restaging it

        if (t + 2 < ntiles) {
            const int k2 = (t + 2) * 64;
            const uint32 koff = (uint32)(cur * 64 * 144);
            #pragma unroll
            for (int q = 0; q < 8; q++) {
                const int r = srow + (q & 3) * 16;
                if (q < 4) {
                    CP_ASYNC16(ks_base + koff + (uint32)(r * 144 + sseg * 16),
                               (const char*)&kh[(size_t)(k2 + r) * HD + sseg * 8]);
                } else {
                    CP_ASYNC16(vp_base + koff + (uint32)(r * 144 + sseg * 16),
                               (const char*)&vt[(size_t)r * SEQ + k2 + sseg * 8]);
                }
            }
            CP_COMMIT();
        }
    }

    const float il0 = 1.0f / l_r[0];
    const float il1 = 1.0f / l_r[1];
    #pragma unroll
    for (int nt = 0; nt < 8; nt++) {
        const int d0 = nt * 8 + 2 * lc;
        *(ull*)&out[((size_t)b * SEQ + row0) * HD + d0] = pk2(o[nt][0] * il0, o[nt][1] * il0);
        *(ull*)&out[((size_t)b * SEQ + row1) * HD + d0] = pk2(o[nt][2] * il1, o[nt][3] * il1);
    }
}

extern "C" void kernel_launch(void* const* d_in, const int* in_sizes, int n_in,
                              void* d_out, int out_size)
{
    const float* x  = (const float*)d_in[0];
    const float* Wq = (const float*)d_in[1];
    const float* Wk = (const float*)d_in[2];
    const float* Wv = (const float*)d_in[3];
    float* out = (float*)d_out;

    rope_table_kernel<<<(SEQ * 32 + 255) / 256, 256>>>();

    dim3 g1(3, (BSZ * SEQ) / 128);
    qkv_rope_kernel<<<g1, 256>>>(x, Wq, Wk, Wv);

    const int smem = 4 * 64 * AW * (int)sizeof(uint32);   // 36864 B
    cudaFuncSetAttribute(attn_kernel, cudaFuncAttributeMaxDynamicSharedMemorySize, smem);
    dim3 g2(SEQ / 64, BSZ);
    attn_kernel<<<g2, 128, smem>>>(out);
}

// round 15
// speedup vs baseline: 2.0243x; 1.0372x over previous
#include <cuda_runtime.h>
#include <cuda_fp16.h>
#include <math.h>

#define BSZ 32
#define SEQ 1024
#define EMB 768
#define HD  64

typedef unsigned long long ull;
typedef unsigned int uint32;

__device__ __forceinline__ ull pk2(float lo, float hi) {
    ull r; asm("mov.b64 %0, {%1, %2};" : "=l"(r) : "f"(lo), "f"(hi)); return r;
}
__device__ __forceinline__ uint32 ph2(float lo, float hi) {
    uint32 r; asm("cvt.rn.f16x2.f32 %0, %1, %2;" : "=r"(r) : "f"(hi), "f"(lo)); return r;
}
__device__ __forceinline__ uint32 h2exp2(uint32 x) {
    uint32 r; asm("ex2.approx.f16x2 %0, %1;" : "=r"(r) : "r"(x)); return r;
}
__device__ __forceinline__ void mma_f16(float c[4],
    uint32 a0, uint32 a1, uint32 a2, uint32 a3, uint32 b0, uint32 b1)
{
    asm volatile(
        "mma.sync.aligned.m16n8k16.row.col.f32.f16.f16.f32 "
        "{%0,%1,%2,%3}, {%4,%5,%6,%7}, {%8,%9}, {%0,%1,%2,%3};"
        : "+f"(c[0]), "+f"(c[1]), "+f"(c[2]), "+f"(c[3])
        : "r"(a0), "r"(a1), "r"(a2), "r"(a3), "r"(b0), "r"(b1));
}
__device__ __forceinline__ uint32 smem_u32(const void* p) {
    uint32 a;
    asm("{ .reg .u64 t; cvta.to.shared.u64 t, %1; cvt.u32.u64 %0, t; }" : "=r"(a) : "l"(p));
    return a;
}
#define CP_ASYNC16(dst, src) \
    asm volatile("cp.async.ca.shared.global [%0], [%1], 16;" :: "r"(dst), "l"(src))
#define CP_COMMIT() asm volatile("cp.async.commit_group;" ::: "memory")
#define CP_WAIT(N)  asm volatile("cp.async.wait_group %0;" :: "n"(N) : "memory")

// fp16 intermediates (q pre-scaled by scale*log2e; v stored transposed [b][h][kv])
__device__ __half g_qh[BSZ * SEQ * HD];
__device__ __half g_kh[BSZ * SEQ * HD];
__device__ __half g_vt[BSZ * HD * SEQ];
__device__ float  g_cos[SEQ * 32];
__device__ float  g_sin[SEQ * 32];

// ---------------------------------------------------------------------------
// Kernel 0: RoPE cos/sin table
// ---------------------------------------------------------------------------
__global__ void rope_table_kernel()
{
    const int t = blockIdx.x * blockDim.x + threadIdx.x;
    if (t >= SEQ * 32) return;
    const int pos = t >> 5;
    const int pr  = t & 31;
    const float theta = expf((float)pr * -0.5756462732485114f);
    float sn, cs;
    sincosf((float)pos * theta, &sn, &cs);
    g_cos[t] = cs;
    g_sin[t] = sn;
}

// ---------------------------------------------------------------------------
// Kernel 1: QKV projection (fp16 HMMA) + RoPE; fp16 outputs (R14, passing).
// ---------------------------------------------------------------------------
#define XW 20

__global__ __launch_bounds__(256) void qkv_rope_kernel(
    const float* __restrict__ x,
    const float* __restrict__ Wq,
    const float* __restrict__ Wk,
    const float* __restrict__ Wv)
{
    const int which = blockIdx.x;
    const float* __restrict__ W = (which == 0) ? Wq : ((which == 1) ? Wk : Wv);

    const int m0 = blockIdx.y * 128;

    __shared__ uint32 xs[2][128 * XW];
    __shared__ uint32 ws[2][64 * XW];

    const int tid    = threadIdx.x;
    const int lane   = tid & 31;
    const int wid    = tid >> 5;
    const int warp_m = wid & 3;
    const int warp_n = wid >> 2;
    const int lr = lane >> 2;
    const int lc = lane & 3;

    const int xrow = tid >> 3;
    const int xkq  = tid & 7;

    uint2 rx[4], rw[2];

    float c[2][4][4];
    #pragma unroll
    for (int mt = 0; mt < 2; mt++)
        #pragma unroll
        for (int nt = 0; nt < 4; nt++)
            #pragma unroll
            for (int r = 0; r < 4; r++) c[mt][nt][r] = 0.f;

    #pragma unroll
    for (int q = 0; q < 4; q++) {
        float4 t = *(const float4*)&x[(size_t)(m0 + xrow + q * 32) * EMB + xkq * 4];
        rx[q] = make_uint2(ph2(t.x, t.y), ph2(t.z, t.w));
    }
    #pragma unroll
    for (int q = 0; q < 2; q++) {
        float4 t = *(const float4*)&W[(size_t)(xrow + q * 32) * EMB + xkq * 4];
        rw[q] = make_uint2(ph2(t.x, t.y), ph2(t.z, t.w));
    }
    #pragma unroll
    for (int q = 0; q < 4; q++)
        *(uint2*)&xs[0][(xrow + q * 32) * XW + xkq * 2] = rx[q];
    #pragma unroll
    for (int q = 0; q < 2; q++)
        *(uint2*)&ws[0][(xrow + q * 32) * XW + xkq * 2] = rw[q];
    __syncthreads();

    const int NCH = EMB / 32;   // 24
    for (int ec = 0; ec < NCH; ec++) {
        const int cur = ec & 1;
        const bool more = (ec + 1 < NCH);
        if (more) {
            const int e1 = (ec + 1) * 32;
            #pragma unroll
            for (int q = 0; q < 4; q++) {
                float4 t = *(const float4*)&x[(size_t)(m0 + xrow + q * 32) * EMB + e1 + xkq * 4];
                rx[q] = make_uint2(ph2(t.x, t.y), ph2(t.z, t.w));
            }
            #pragma unroll
            for (int q = 0; q < 2; q++) {
                float4 t = *(const float4*)&W[(size_t)(xrow + q * 32) * EMB + e1 + xkq * 4];
                rw[q] = make_uint2(ph2(t.x, t.y), ph2(t.z, t.w));
            }
        }

        #pragma unroll
        for (int ks = 0; ks < 2; ks++) {
            const int kb = ks * 8;
            uint32 a[2][4];
            #pragma unroll
            for (int mt = 0; mt < 2; mt++) {
                const int rb = warp_m * 32 + mt * 16 + lr;
                a[mt][0] = xs[cur][rb * XW + kb + lc];
                a[mt][1] = xs[cur][(rb + 8) * XW + kb + lc];
                a[mt][2] = xs[cur][rb * XW + kb + lc + 4];
                a[mt][3] = xs[cur][(rb + 8) * XW + kb + lc + 4];
            }
            uint32 bb[4][2];
            #pragma unroll
            for (int nt = 0; nt < 4; nt++) {
                const int nb = warp_n * 32 + nt * 8 + lr;
                bb[nt][0] = ws[cur][nb * XW + kb + lc];
                bb[nt][1] = ws[cur][nb * XW + kb + lc + 4];
            }
            #pragma unroll
            for (int mt = 0; mt < 2; mt++)
                #pragma unroll
                for (int nt = 0; nt < 4; nt++)
                    mma_f16(c[mt][nt], a[mt][0], a[mt][1], a[mt][2], a[mt][3],
                            bb[nt][0], bb[nt][1]);
        }

        if (more) {
            const int nxt = cur ^ 1;
            #pragma unroll
            for (int q = 0; q < 4; q++)
                *(uint2*)&xs[nxt][(xrow + q * 32) * XW + xkq * 2] = rx[q];
            #pragma unroll
            for (int q = 0; q < 2; q++)
                *(uint2*)&ws[nxt][(xrow + q * 32) * XW + xkq * 2] = rw[q];
            __syncthreads();
        }
    }

    if (which < 2) {
        const float sc = (which == 0) ? (0.03608439182435161f * 1.4426950408889634f) : 1.0f;
        __half* outp = (which == 0) ? g_qh : g_kh;
        #pragma unroll
        for (int mt = 0; mt < 2; mt++) {
            const int r0 = m0 + warp_m * 32 + mt * 16 + lr;
            const int r1 = r0 + 8;
            const int p0 = r0 & (SEQ - 1);
            const int p1 = r1 & (SEQ - 1);
            #pragma unroll
            for (int nt = 0; nt < 4; nt++) {
                const int d0   = warp_n * 32 + nt * 8 + 2 * lc;
                const int pair = d0 >> 1;
                {
                    const float cs = g_cos[p0 * 32 + pair];
                    const float sn = g_sin[p0 * 32 + pair];
                    const float av = c[mt][nt][0], bv = c[mt][nt][1];
                    *(uint32*)&outp[(size_t)r0 * HD + d0] =
                        ph2((av * cs - bv * sn) * sc, (bv * cs + av * sn) * sc);
                }
                {
                    const float cs = g_cos[p1 * 32 + pair];
                    const float sn = g_sin[p1 * 32 + pair];
                    const float av = c[mt][nt][2], bv = c[mt][nt][3];
                    *(uint32*)&outp[(size_t)r1 * HD + d0] =
                        ph2((av * cs - bv * sn) * sc, (bv * cs + av * sn) * sc);
                }
            }
        }
    } else {
        #pragma unroll
        for (int mt = 0; mt < 2; mt++) {
            const int r0  = m0 + warp_m * 32 + mt * 16 + lr;
            const int b   = r0 >> 10;
            const int kv0 = r0 & (SEQ - 1);
            __half* vb = g_vt + (size_t)b * HD * SEQ;
            #pragma unroll
            for (int nt = 0; nt < 4; nt++) {
                const int d0 = warp_n * 32 + nt * 8 + 2 * lc;
                vb[(size_t)d0 * SEQ + kv0]           = __float2half_rn(c[mt][nt][0]);
                vb[(size_t)(d0 + 1) * SEQ + kv0]     = __float2half_rn(c[mt][nt][1]);
                vb[(size_t)d0 * SEQ + kv0 + 8]       = __float2half_rn(c[mt][nt][2]);
                vb[(size_t)(d0 + 1) * SEQ + kv0 + 8] = __float2half_rn(c[mt][nt][3]);
            }
        }
    }
}

// ---------------------------------------------------------------------------
// Kernel 2: causal flash attention — fp16 in, cp.async K/V, register P,
//   f16x2 exp2, row-sums via ones-MMA on the tensor pipe.
// ---------------------------------------------------------------------------
#define AW 36    // words per smem row (144 B)
#define ONE2 0x3C003C00u   // (1.0h, 1.0h)

__global__ __launch_bounds__(128) void attn_kernel(float* __restrict__ out)
{
    extern __shared__ uint32 smu[];
    uint32* Ks = smu;                     // [2][64 kv][36w] fp16 [kv][h]
    uint32* Vp = Ks + 2 * 64 * AW;        // [2][64 h][36w]  fp16 [h][kvpair]
    const uint32 ks_base = smem_u32(Ks);
    const uint32 vp_base = smem_u32(Vp);

    const int b  = blockIdx.y;
    const int qt = (SEQ / 64 - 1) - blockIdx.x;
    const int q0 = qt * 64;

    const __half* __restrict__ qh = g_qh + ((size_t)b * SEQ + q0) * HD;
    const __half* __restrict__ kh = g_kh + (size_t)b * SEQ * HD;
    const __half* __restrict__ vt = g_vt + (size_t)b * HD * SEQ;

    const int tid  = threadIdx.x;
    const int lane = tid & 31;
    const int w    = tid >> 5;
    const int lr   = lane >> 2;
    const int lc   = lane & 3;

    const int srow = tid >> 3;
    const int sseg = tid & 7;

    // ---- Q fragments (pre-scaled fp16, direct global loads) ----
    uint32 qa[4][4];
    {
        const __half* q0p = qh + (size_t)(w * 16 + lr) * HD;
        const __half* q1p = q0p + 8 * HD;
        #pragma unroll
        for (int ks = 0; ks < 4; ks++) {
            const int k = ks * 16 + 2 * lc;
            qa[ks][0] = *(const uint32*)&q0p[k];
            qa[ks][1] = *(const uint32*)&q1p[k];
            qa[ks][2] = *(const uint32*)&q0p[k + 8];
            qa[ks][3] = *(const uint32*)&q1p[k + 8];
        }
    }

    const int ntiles = qt + 1;

    // ---- prologue: stage tiles 0 (and 1) ----
    {
        #pragma unroll
        for (int q = 0; q < 8; q++) {
            const int r = srow + (q & 3) * 16;
            if (q < 4) {
                CP_ASYNC16(ks_base + (uint32)(r * 144 + sseg * 16),
                           (const char*)&kh[(size_t)r * HD + sseg * 8]);
            } else {
                CP_ASYNC16(vp_base + (uint32)(r * 144 + sseg * 16),
                           (const char*)&vt[(size_t)r * SEQ + sseg * 8]);
            }
        }
        CP_COMMIT();
        if (ntiles > 1) {
            #pragma unroll
            for (int q = 0; q < 8; q++) {
                const int r = srow + (q & 3) * 16;
                if (q < 4) {
                    CP_ASYNC16(ks_base + (uint32)(64 * 144 + r * 144 + sseg * 16),
                               (const char*)&kh[(size_t)(64 + r) * HD + sseg * 8]);
                } else {
                    CP_ASYNC16(vp_base + (uint32)(64 * 144 + r * 144 + sseg * 16),
                               (const char*)&vt[(size_t)r * SEQ + 64 + sseg * 8]);
                }
            }
            CP_COMMIT();
        }
    }

    float m_r[2] = {-1e30f, -1e30f};
    float l_r[2] = {0.f, 0.f};
    float o[8][4];
    #pragma unroll
    for (int nt = 0; nt < 8; nt++)
        #pragma unroll
        for (int r = 0; r < 4; r++) o[nt][r] = 0.f;

    const int row0 = q0 + w * 16 + lr;
    const int row1 = row0 + 8;

    for (int t = 0; t < ntiles; t++) {
        const int cur = t & 1;
        uint32* Kc = Ks + cur * 64 * AW;
        uint32* Vc = Vp + cur * 64 * AW;

        if (t + 1 < ntiles) { CP_WAIT(1); } else { CP_WAIT(0); }
        __syncthreads();

        // ---- S = Q K^T (log2 softmax domain) ----
        float s[8][4];
        #pragma unroll
        for (int nt = 0; nt < 8; nt++)
            #pragma unroll
            for (int r = 0; r < 4; r++) s[nt][r] = 0.f;

        #pragma unroll
        for (int ks = 0; ks < 4; ks++) {
            const int kb = ks * 8;
            #pragma unroll
            for (int nt = 0; nt < 8; nt++) {
                const int nb = nt * 8 + lr;
                const uint32 b0 = Kc[nb * AW + kb + lc];
                const uint32 b1 = Kc[nb * AW + kb + lc + 4];
                mma_f16(s[nt], qa[ks][0], qa[ks][1], qa[ks][2], qa[ks][3], b0, b1);
            }
        }

        if (t == qt) {
            #pragma unroll
            for (int nt = 0; nt < 8; nt++) {
                const int col = q0 + nt * 8 + 2 * lc;
                #pragma unroll
                for (int r = 0; r < 4; r++) {
                    const int gr = (r < 2) ? row0 : row1;
                    const int gc = col + (r & 1);
                    if (gc > gr) s[nt][r] = -1e30f;
                }
            }
        }

        // ---- online softmax: max (fp32) then f16x2 exp2 ----
        float alpha[2], mnewv[2];
        #pragma unroll
        for (int h = 0; h < 2; h++) {
            float rm = -1e30f;
            #pragma unroll
            for (int nt = 0; nt < 8; nt++)
                rm = fmaxf(rm, fmaxf(s[nt][2 * h], s[nt][2 * h + 1]));
            rm = fmaxf(rm, __shfl_xor_sync(0xffffffffu, rm, 1));
            rm = fmaxf(rm, __shfl_xor_sync(0xffffffffu, rm, 2));
            const float mnew = fmaxf(m_r[h], rm);
            alpha[h] = exp2f(m_r[h] - mnew);
            m_r[h] = mnew;
            mnewv[h] = mnew;
        }

        // P = exp2(s - m) computed in packed fp16 (one MUFU per pair)
        uint32 pA[8][2];
        #pragma unroll
        for (int nt = 0; nt < 8; nt++) {
            pA[nt][0] = h2exp2(ph2(s[nt][0] - mnewv[0], s[nt][1] - mnewv[0]));
            pA[nt][1] = h2exp2(ph2(s[nt][2] - mnewv[1], s[nt][3] - mnewv[1]));
        }

        // row sums via ones-MMA (exact fp32 sum of the fp16 P actually used)
        float rsum[4] = {0.f, 0.f, 0.f, 0.f};
        #pragma unroll
        for (int ks = 0; ks < 4; ks++)
            mma_f16(rsum, pA[2 * ks][0], pA[2 * ks][1],
                    pA[2 * ks + 1][0], pA[2 * ks + 1][1], ONE2, ONE2);
        l_r[0] = l_r[0] * alpha[0] + rsum[0];
        l_r[1] = l_r[1] * alpha[1] + rsum[2];

        if (__any_sync(0xffffffffu, (alpha[0] < 1.0f) | (alpha[1] < 1.0f))) {
            #pragma unroll
            for (int nt = 0; nt < 8; nt++) {
                o[nt][0] *= alpha[0]; o[nt][1] *= alpha[0];
                o[nt][2] *= alpha[1]; o[nt][3] *= alpha[1];
            }
        }

        // ---- O += P V ----
        #pragma unroll
        for (int ks = 0; ks < 4; ks++) {
            const int kb = ks * 8;
            const uint32 a0 = pA[2 * ks][0];
            const uint32 a1 = pA[2 * ks][1];
            const uint32 a2 = pA[2 * ks + 1][0];
            const uint32 a3 = pA[2 * ks + 1][1];
            #pragma unroll
            for (int nt = 0; nt < 8; nt++) {
                const int nb = nt * 8 + lr;
                const uint32 b0 = Vc[nb * AW + kb + lc];
                const uint32 b1 = Vc[nb * AW + kb + lc + 4];
                mma_f16(o[nt], a0, a1, a2, a3, b0, b1);
            }
        }

        __syncthreads();

        if (t + 2 < ntiles) {
            const int k2 = (t + 2) * 64;
            const uint32 koff = (uint32)(cur * 64 * 144);
            #pragma unroll
            for (int q = 0; q < 8; q++) {
                const int r = srow + (q & 3) * 16;
                if (q < 4) {
                    CP_ASYNC16(ks_base + koff + (uint32)(r * 144 + sseg * 16),
                               (const char*)&kh[(size_t)(k2 + r) * HD + sseg * 8]);
                } else {
                    CP_ASYNC16(vp_base + koff + (uint32)(r * 144 + sseg * 16),
                               (const char*)&vt[(size_t)r * SEQ + k2 + sseg * 8]);
                }
            }
            CP_COMMIT();
        }
    }

    const float il0 = 1.0f / l_r[0];
    const float il1 = 1.0f / l_r[1];
    #pragma unroll
    for (int nt = 0; nt < 8; nt++) {
        const int d0 = nt * 8 + 2 * lc;
        *(ull*)&out[((size_t)b * SEQ + row0) * HD + d0] = pk2(o[nt][0] * il0, o[nt][1] * il0);
        *(ull*)&out[((size_t)b * SEQ + row1) * HD + d0] = pk2(o[nt][2] * il1, o[nt][3] * il1);
    }
}

extern "C" void kernel_launch(void* const* d_in, const int* in_sizes, int n_in,
                              void* d_out, int out_size)
{
    const float* x  = (const float*)d_in[0];
    const float* Wq = (const float*)d_in[1];
    const float* Wk = (const float*)d_in[2];
    const float* Wv = (const float*)d_in[3];
    float* out = (float*)d_out;

    rope_table_kernel<<<(SEQ * 32 + 255) / 256, 256>>>();

    dim3 g1(3, (BSZ * SEQ) / 128);
    qkv_rope_kernel<<<g1, 256>>>(x, Wq, Wk, Wv);

    const int smem = 4 * 64 * AW * (int)sizeof(uint32);   // 36864 B
    cudaFuncSetAttribute(attn_kernel, cudaFuncAttributeMaxDynamicSharedMemorySize, smem);
    dim3 g2(SEQ / 64, BSZ);
    attn_kernel<<<g2, 128, smem>>>(out);
}

// round 16
// speedup vs baseline: 2.0249x; 1.0003x over previous
#include <cuda_runtime.h>
#include <cuda_fp16.h>
#include <math.h>

#define BSZ 32
#define SEQ 1024
#define EMB 768
#define HD  64

typedef unsigned long long ull;
typedef unsigned int uint32;

__device__ __forceinline__ ull pk2(float lo, float hi) {
    ull r; asm("mov.b64 %0, {%1, %2};" : "=l"(r) : "f"(lo), "f"(hi)); return r;
}
__device__ __forceinline__ uint32 ph2(float lo, float hi) {
    uint32 r; asm("cvt.rn.f16x2.f32 %0, %1, %2;" : "=r"(r) : "f"(hi), "f"(lo)); return r;
}
__device__ __forceinline__ uint32 h2exp2(uint32 x) {
    uint32 r; asm("ex2.approx.f16x2 %0, %1;" : "=r"(r) : "r"(x)); return r;
}
__device__ __forceinline__ void mma_f16(float c[4],
    uint32 a0, uint32 a1, uint32 a2, uint32 a3, uint32 b0, uint32 b1)
{
    asm volatile(
        "mma.sync.aligned.m16n8k16.row.col.f32.f16.f16.f32 "
        "{%0,%1,%2,%3}, {%4,%5,%6,%7}, {%8,%9}, {%0,%1,%2,%3};"
        : "+f"(c[0]), "+f"(c[1]), "+f"(c[2]), "+f"(c[3])
        : "r"(a0), "r"(a1), "r"(a2), "r"(a3), "r"(b0), "r"(b1));
}
// fp16-accumulate variant: C/D are 2x f16x2 regs
__device__ __forceinline__ void mma_f16c16(uint32& c0, uint32& c1,
    uint32 a0, uint32 a1, uint32 a2, uint32 a3, uint32 b0, uint32 b1)
{
    asm volatile(
        "mma.sync.aligned.m16n8k16.row.col.f16.f16.f16.f16 "
        "{%0,%1}, {%2,%3,%4,%5}, {%6,%7}, {%0,%1};"
        : "+r"(c0), "+r"(c1)
        : "r"(a0), "r"(a1), "r"(a2), "r"(a3), "r"(b0), "r"(b1));
}
__device__ __forceinline__ uint32 smem_u32(const void* p) {
    uint32 a;
    asm("{ .reg .u64 t; cvta.to.shared.u64 t, %1; cvt.u32.u64 %0, t; }" : "=r"(a) : "l"(p));
    return a;
}
#define CP_ASYNC16(dst, src) \
    asm volatile("cp.async.ca.shared.global [%0], [%1], 16;" :: "r"(dst), "l"(src))
#define CP_COMMIT() asm volatile("cp.async.commit_group;" ::: "memory")
#define CP_WAIT(N)  asm volatile("cp.async.wait_group %0;" :: "n"(N) : "memory")

// fp16 intermediates (q pre-scaled by scale*log2e; v stored transposed [b][h][kv])
__device__ __half g_qh[BSZ * SEQ * HD];
__device__ __half g_kh[BSZ * SEQ * HD];
__device__ __half g_vt[BSZ * HD * SEQ];
__device__ float  g_cos[SEQ * 32];
__device__ float  g_sin[SEQ * 32];

// ---------------------------------------------------------------------------
// Kernel 0: RoPE cos/sin table
// ---------------------------------------------------------------------------
__global__ void rope_table_kernel()
{
    const int t = blockIdx.x * blockDim.x + threadIdx.x;
    if (t >= SEQ * 32) return;
    const int pos = t >> 5;
    const int pr  = t & 31;
    const float theta = expf((float)pr * -0.5756462732485114f);
    float sn, cs;
    sincosf((float)pos * theta, &sn, &cs);
    g_cos[t] = cs;
    g_sin[t] = sn;
}

// ---------------------------------------------------------------------------
// Kernel 1: QKV projection (fp16 HMMA) + RoPE; fp16 outputs (R14/15, passing).
// ---------------------------------------------------------------------------
#define XW 20

__global__ __launch_bounds__(256) void qkv_rope_kernel(
    const float* __restrict__ x,
    const float* __restrict__ Wq,
    const float* __restrict__ Wk,
    const float* __restrict__ Wv)
{
    const int which = blockIdx.x;
    const float* __restrict__ W = (which == 0) ? Wq : ((which == 1) ? Wk : Wv);

    const int m0 = blockIdx.y * 128;

    __shared__ uint32 xs[2][128 * XW];
    __shared__ uint32 ws[2][64 * XW];

    const int tid    = threadIdx.x;
    const int lane   = tid & 31;
    const int wid    = tid >> 5;
    const int warp_m = wid & 3;
    const int warp_n = wid >> 2;
    const int lr = lane >> 2;
    const int lc = lane & 3;

    const int xrow = tid >> 3;
    const int xkq  = tid & 7;

    uint2 rx[4], rw[2];

    float c[2][4][4];
    #pragma unroll
    for (int mt = 0; mt < 2; mt++)
        #pragma unroll
        for (int nt = 0; nt < 4; nt++)
            #pragma unroll
            for (int r = 0; r < 4; r++) c[mt][nt][r] = 0.f;

    #pragma unroll
    for (int q = 0; q < 4; q++) {
        float4 t = *(const float4*)&x[(size_t)(m0 + xrow + q * 32) * EMB + xkq * 4];
        rx[q] = make_uint2(ph2(t.x, t.y), ph2(t.z, t.w));
    }
    #pragma unroll
    for (int q = 0; q < 2; q++) {
        float4 t = *(const float4*)&W[(size_t)(xrow + q * 32) * EMB + xkq * 4];
        rw[q] = make_uint2(ph2(t.x, t.y), ph2(t.z, t.w));
    }
    #pragma unroll
    for (int q = 0; q < 4; q++)
        *(uint2*)&xs[0][(xrow + q * 32) * XW + xkq * 2] = rx[q];
    #pragma unroll
    for (int q = 0; q < 2; q++)
        *(uint2*)&ws[0][(xrow + q * 32) * XW + xkq * 2] = rw[q];
    __syncthreads();

    const int NCH = EMB / 32;   // 24
    for (int ec = 0; ec < NCH; ec++) {
        const int cur = ec & 1;
        const bool more = (ec + 1 < NCH);
        if (more) {
            const int e1 = (ec + 1) * 32;
            #pragma unroll
            for (int q = 0; q < 4; q++) {
                float4 t = *(const float4*)&x[(size_t)(m0 + xrow + q * 32) * EMB + e1 + xkq * 4];
                rx[q] = make_uint2(ph2(t.x, t.y), ph2(t.z, t.w));
            }
            #pragma unroll
            for (int q = 0; q < 2; q++) {
                float4 t = *(const float4*)&W[(size_t)(xrow + q * 32) * EMB + e1 + xkq * 4];
                rw[q] = make_uint2(ph2(t.x, t.y), ph2(t.z, t.w));
            }
        }

        #pragma unroll
        for (int ks = 0; ks < 2; ks++) {
            const int kb = ks * 8;
            uint32 a[2][4];
            #pragma unroll
            for (int mt = 0; mt < 2; mt++) {
                const int rb = warp_m * 32 + mt * 16 + lr;
                a[mt][0] = xs[cur][rb * XW + kb + lc];
                a[mt][1] = xs[cur][(rb + 8) * XW + kb + lc];
                a[mt][2] = xs[cur][rb * XW + kb + lc + 4];
                a[mt][3] = xs[cur][(rb + 8) * XW + kb + lc + 4];
            }
            uint32 bb[4][2];
            #pragma unroll
            for (int nt = 0; nt < 4; nt++) {
                const int nb = warp_n * 32 + nt * 8 + lr;
                bb[nt][0] = ws[cur][nb * XW + kb + lc];
                bb[nt][1] = ws[cur][nb * XW + kb + lc + 4];
            }
            #pragma unroll
            for (int mt = 0; mt < 2; mt++)
                #pragma unroll
                for (int nt = 0; nt < 4; nt++)
                    mma_f16(c[mt][nt], a[mt][0], a[mt][1], a[mt][2], a[mt][3],
                            bb[nt][0], bb[nt][1]);
        }

        if (more) {
            const int nxt = cur ^ 1;
            #pragma unroll
            for (int q = 0; q < 4; q++)
                *(uint2*)&xs[nxt][(xrow + q * 32) * XW + xkq * 2] = rx[q];
            #pragma unroll
            for (int q = 0; q < 2; q++)
                *(uint2*)&ws[nxt][(xrow + q * 32) * XW + xkq * 2] = rw[q];
            __syncthreads();
        }
    }

    if (which < 2) {
        const float sc = (which == 0) ? (0.03608439182435161f * 1.4426950408889634f) : 1.0f;
        __half* outp = (which == 0) ? g_qh : g_kh;
        #pragma unroll
        for (int mt = 0; mt < 2; mt++) {
            const int r0 = m0 + warp_m * 32 + mt * 16 + lr;
            const int r1 = r0 + 8;
            const int p0 = r0 & (SEQ - 1);
            const int p1 = r1 & (SEQ - 1);
            #pragma unroll
            for (int nt = 0; nt < 4; nt++) {
                const int d0   = warp_n * 32 + nt * 8 + 2 * lc;
                const int pair = d0 >> 1;
                {
                    const float cs = g_cos[p0 * 32 + pair];
                    const float sn = g_sin[p0 * 32 + pair];
                    const float av = c[mt][nt][0], bv = c[mt][nt][1];
                    *(uint32*)&outp[(size_t)r0 * HD + d0] =
                        ph2((av * cs - bv * sn) * sc, (bv * cs + av * sn) * sc);
                }
                {
                    const float cs = g_cos[p1 * 32 + pair];
                    const float sn = g_sin[p1 * 32 + pair];
                    const float av = c[mt][nt][2], bv = c[mt][nt][3];
                    *(uint32*)&outp[(size_t)r1 * HD + d0] =
                        ph2((av * cs - bv * sn) * sc, (bv * cs + av * sn) * sc);
                }
            }
        }
    } else {
        #pragma unroll
        for (int mt = 0; mt < 2; mt++) {
            const int r0  = m0 + warp_m * 32 + mt * 16 + lr;
            const int b   = r0 >> 10;
            const int kv0 = r0 & (SEQ - 1);
            __half* vb = g_vt + (size_t)b * HD * SEQ;
            #pragma unroll
            for (int nt = 0; nt < 4; nt++) {
                const int d0 = warp_n * 32 + nt * 8 + 2 * lc;
                vb[(size_t)d0 * SEQ + kv0]           = __float2half_rn(c[mt][nt][0]);
                vb[(size_t)(d0 + 1) * SEQ + kv0]     = __float2half_rn(c[mt][nt][1]);
                vb[(size_t)d0 * SEQ + kv0 + 8]       = __float2half_rn(c[mt][nt][2]);
                vb[(size_t)(d0 + 1) * SEQ + kv0 + 8] = __float2half_rn(c[mt][nt][3]);
            }
        }
    }
}

// ---------------------------------------------------------------------------
// Kernel 2: causal flash attention — fp16 S accumulation, packed softmax,
//   cp.async K/V, register P, ones-MMA row sums. 5 CTAs/SM target.
// ---------------------------------------------------------------------------
#define AW 36    // words per smem row (144 B)
#define ONE2 0x3C003C00u   // (1.0h, 1.0h)
#define NINF16 0xFC00u     // fp16 -inf

__global__ __launch_bounds__(128, 5) void attn_kernel(float* __restrict__ out)
{
    extern __shared__ uint32 smu[];
    uint32* Ks = smu;                     // [2][64 kv][36w] fp16 [kv][h]
    uint32* Vp = Ks + 2 * 64 * AW;        // [2][64 h][36w]  fp16 [h][kvpair]
    const uint32 ks_base = smem_u32(Ks);
    const uint32 vp_base = smem_u32(Vp);

    const int b  = blockIdx.y;
    const int qt = (SEQ / 64 - 1) - blockIdx.x;
    const int q0 = qt * 64;

    const __half* __restrict__ qh = g_qh + ((size_t)b * SEQ + q0) * HD;
    const __half* __restrict__ kh = g_kh + (size_t)b * SEQ * HD;
    const __half* __restrict__ vt = g_vt + (size_t)b * HD * SEQ;

    const int tid  = threadIdx.x;
    const int lane = tid & 31;
    const int w    = tid >> 5;
    const int lr   = lane >> 2;
    const int lc   = lane & 3;

    const int srow = tid >> 3;
    const int sseg = tid & 7;

    // ---- Q fragments (pre-scaled fp16, direct global loads) ----
    uint32 qa[4][4];
    {
        const __half* q0p = qh + (size_t)(w * 16 + lr) * HD;
        const __half* q1p = q0p + 8 * HD;
        #pragma unroll
        for (int ks = 0; ks < 4; ks++) {
            const int k = ks * 16 + 2 * lc;
            qa[ks][0] = *(const uint32*)&q0p[k];
            qa[ks][1] = *(const uint32*)&q1p[k];
            qa[ks][2] = *(const uint32*)&q0p[k + 8];
            qa[ks][3] = *(const uint32*)&q1p[k + 8];
        }
    }

    const int ntiles = qt + 1;

    // ---- prologue: stage tiles 0 (and 1) ----
    {
        #pragma unroll
        for (int q = 0; q < 8; q++) {
            const int r = srow + (q & 3) * 16;
            if (q < 4) {
                CP_ASYNC16(ks_base + (uint32)(r * 144 + sseg * 16),
                           (const char*)&kh[(size_t)r * HD + sseg * 8]);
            } else {
                CP_ASYNC16(vp_base + (uint32)(r * 144 + sseg * 16),
                           (const char*)&vt[(size_t)r * SEQ + sseg * 8]);
            }
        }
        CP_COMMIT();
        if (ntiles > 1) {
            #pragma unroll
            for (int q = 0; q < 8; q++) {
                const int r = srow + (q & 3) * 16;
                if (q < 4) {
                    CP_ASYNC16(ks_base + (uint32)(64 * 144 + r * 144 + sseg * 16),
                               (const char*)&kh[(size_t)(64 + r) * HD + sseg * 8]);
                } else {
                    CP_ASYNC16(vp_base + (uint32)(64 * 144 + r * 144 + sseg * 16),
                               (const char*)&vt[(size_t)r * SEQ + 64 + sseg * 8]);
                }
            }
            CP_COMMIT();
        }
    }

    float m_r[2] = {-1e30f, -1e30f};
    float l_r[2] = {0.f, 0.f};
    float o[8][4];
    #pragma unroll
    for (int nt = 0; nt < 8; nt++)
        #pragma unroll
        for (int r = 0; r < 4; r++) o[nt][r] = 0.f;

    const int row0 = q0 + w * 16 + lr;
    const int row1 = row0 + 8;

    for (int t = 0; t < ntiles; t++) {
        const int cur = t & 1;
        uint32* Kc = Ks + cur * 64 * AW;
        uint32* Vc = Vp + cur * 64 * AW;

        if (t + 1 < ntiles) { CP_WAIT(1); } else { CP_WAIT(0); }
        __syncthreads();

        // ---- S = Q K^T, fp16 accumulation (log2 softmax domain) ----
        // s2[nt][0] = (row lr: col 2lc, 2lc+1), s2[nt][1] = (row lr+8: same cols)
        uint32 s2[8][2];
        #pragma unroll
        for (int nt = 0; nt < 8; nt++) { s2[nt][0] = 0u; s2[nt][1] = 0u; }

        #pragma unroll
        for (int ks = 0; ks < 4; ks++) {
            const int kb = ks * 8;
            #pragma unroll
            for (int nt = 0; nt < 8; nt++) {
                const int nb = nt * 8 + lr;
                const uint32 b0 = Kc[nb * AW + kb + lc];
                const uint32 b1 = Kc[nb * AW + kb + lc + 4];
                mma_f16c16(s2[nt][0], s2[nt][1],
                           qa[ks][0], qa[ks][1], qa[ks][2], qa[ks][3], b0, b1);
            }
        }

        // causal mask (diagonal tile only), per fp16 half
        if (t == qt) {
            #pragma unroll
            for (int nt = 0; nt < 8; nt++) {
                const int col = q0 + nt * 8 + 2 * lc;
                __half2 v0 = *(__half2*)&s2[nt][0];
                __half2 v1 = *(__half2*)&s2[nt][1];
                if (col     > row0) v0.x = __ushort_as_half((unsigned short)NINF16);
                if (col + 1 > row0) v0.y = __ushort_as_half((unsigned short)NINF16);
                if (col     > row1) v1.x = __ushort_as_half((unsigned short)NINF16);
                if (col + 1 > row1) v1.y = __ushort_as_half((unsigned short)NINF16);
                *(__half2*)&s2[nt][0] = v0;
                *(__half2*)&s2[nt][1] = v1;
            }
        }

        // ---- online softmax: packed hmax2, then f16x2 exp2 ----
        __half2 pm0 = *(__half2*)&s2[0][0];
        __half2 pm1 = *(__half2*)&s2[0][1];
        #pragma unroll
        for (int nt = 1; nt < 8; nt++) {
            pm0 = __hmax2(pm0, *(__half2*)&s2[nt][0]);
            pm1 = __hmax2(pm1, *(__half2*)&s2[nt][1]);
        }
        float rm0 = __half2float(__hmax(pm0.x, pm0.y));
        float rm1 = __half2float(__hmax(pm1.x, pm1.y));
        rm0 = fmaxf(rm0, __shfl_xor_sync(0xffffffffu, rm0, 1));
        rm0 = fmaxf(rm0, __shfl_xor_sync(0xffffffffu, rm0, 2));
        rm1 = fmaxf(rm1, __shfl_xor_sync(0xffffffffu, rm1, 1));
        rm1 = fmaxf(rm1, __shfl_xor_sync(0xffffffffu, rm1, 2));

        const float mnew0 = fmaxf(m_r[0], rm0);
        const float mnew1 = fmaxf(m_r[1], rm1);
        const float alpha0 = exp2f(m_r[0] - mnew0);
        const float alpha1 = exp2f(m_r[1] - mnew1);
        m_r[0] = mnew0; m_r[1] = mnew1;

        const __half2 mh0 = __float2half2_rn(mnew0);
        const __half2 mh1 = __float2half2_rn(mnew1);

        // P = exp2(s - m): one hsub2 + one MUFU per pair; output IS the A-fragment
        uint32 pA[8][2];
        #pragma unroll
        for (int nt = 0; nt < 8; nt++) {
            __half2 d0 = __hsub2(*(__half2*)&s2[nt][0], mh0);
            __half2 d1 = __hsub2(*(__half2*)&s2[nt][1], mh1);
            pA[nt][0] = h2exp2(*(uint32*)&d0);
            pA[nt][1] = h2exp2(*(uint32*)&d1);
        }

        // row sums via ones-MMA (fp32 C)
        float rsum[4] = {0.f, 0.f, 0.f, 0.f};
        #pragma unroll
        for (int ks = 0; ks < 4; ks++)
            mma_f16(rsum, pA[2 * ks][0], pA[2 * ks][1],
                    pA[2 * ks + 1][0], pA[2 * ks + 1][1], ONE2, ONE2);
        l_r[0] = l_r[0] * alpha0 + rsum[0];
        l_r[1] = l_r[1] * alpha1 + rsum[2];

        if (__any_sync(0xffffffffu, (alpha0 < 1.0f) | (alpha1 < 1.0f))) {
            #pragma unroll
            for (int nt = 0; nt < 8; nt++) {
                o[nt][0] *= alpha0; o[nt][1] *= alpha0;
                o[nt][2] *= alpha1; o[nt][3] *= alpha1;
            }
        }

        // ---- O += P V (fp32 accumulation) ----
        #pragma unroll
        for (int ks = 0; ks < 4; ks++) {
            const int kb = ks * 8;
            const uint32 a0 = pA[2 * ks][0];
            const uint32 a1 = pA[2 * ks][1];
            const uint32 a2 = pA[2 * ks + 1][0];
            const uint32 a3 = pA[2 * ks + 1][1];
            #pragma unroll
            for (int nt = 0; nt < 8; nt++) {
                const int nb = nt * 8 + lr;
                const uint32 b0 = Vc[nb * AW + kb + lc];
                const uint32 b1 = Vc[nb * AW + kb + lc + 4];
                mma_f16(o[nt], a0, a1, a2, a3, b0, b1);
            }
        }

        __syncthreads();

        if (t + 2 < ntiles) {
            const int k2 = (t + 2) * 64;
            const uint32 koff = (uint32)(cur * 64 * 144);
            #pragma unroll
            for (int q = 0; q < 8; q++) {
                const int r = srow + (q & 3) * 16;
                if (q < 4) {
                    CP_ASYNC16(ks_base + koff + (uint32)(r * 144 + sseg * 16),
                               (const char*)&kh[(size_t)(k2 + r) * HD + sseg * 8]);
                } else {
                    CP_ASYNC16(vp_base + koff + (uint32)(r * 144 + sseg * 16),
                               (const char*)&vt[(size_t)r * SEQ + k2 + sseg * 8]);
                }
            }
            CP_COMMIT();
        }
    }

    const float il0 = 1.0f / l_r[0];
    const float il1 = 1.0f / l_r[1];
    #pragma unroll
    for (int nt = 0; nt < 8; nt++) {
        const int d0 = nt * 8 + 2 * lc;
        *(ull*)&out[((size_t)b * SEQ + row0) * HD + d0] = pk2(o[nt][0] * il0, o[nt][1] * il0);
        *(ull*)&out[((size_t)b * SEQ + row1) * HD + d0] = pk2(o[nt][2] * il1, o[nt][3] * il1);
    }
}

extern "C" void kernel_launch(void* const* d_in, const int* in_sizes, int n_in,
                              void* d_out, int out_size)
{
    const float* x  = (const float*)d_in[0];
    const float* Wq = (const float*)d_in[1];
    const float* Wk = (const float*)d_in[2];
    const float* Wv = (const float*)d_in[3];
    float* out = (float*)d_out;

    rope_table_kernel<<<(SEQ * 32 + 255) / 256, 256>>>();

    dim3 g1(3, (BSZ * SEQ) / 128);
    qkv_rope_kernel<<<g1, 256>>>(x, Wq, Wk, Wv);

    const int smem = 4 * 64 * AW * (int)sizeof(uint32);   // 36864 B
    cudaFuncSetAttribute(attn_kernel, cudaFuncAttributeMaxDynamicSharedMemorySize, smem);
    dim3 g2(SEQ / 64, BSZ);
    attn_kernel<<<g2, 128, smem>>>(out);
}

// round 17
// speedup vs baseline: 2.0891x; 1.0317x over previous
#include <cuda_runtime.h>
#include <cuda_fp16.h>
#include <math.h>

#define BSZ 32
#define SEQ 1024
#define EMB 768
#define HD  64

typedef unsigned long long ull;
typedef unsigned int uint32;

__device__ __forceinline__ ull pk2(float lo, float hi) {
    ull r; asm("mov.b64 %0, {%1, %2};" : "=l"(r) : "f"(lo), "f"(hi)); return r;
}
__device__ __forceinline__ uint32 ph2(float lo, float hi) {
    uint32 r; asm("cvt.rn.f16x2.f32 %0, %1, %2;" : "=r"(r) : "f"(hi), "f"(lo)); return r;
}
__device__ __forceinline__ uint32 h2exp2(uint32 x) {
    uint32 r; asm("ex2.approx.f16x2 %0, %1;" : "=r"(r) : "r"(x)); return r;
}
__device__ __forceinline__ void mma_f16(float c[4],
    uint32 a0, uint32 a1, uint32 a2, uint32 a3, uint32 b0, uint32 b1)
{
    asm volatile(
        "mma.sync.aligned.m16n8k16.row.col.f32.f16.f16.f32 "
        "{%0,%1,%2,%3}, {%4,%5,%6,%7}, {%8,%9}, {%0,%1,%2,%3};"
        : "+f"(c[0]), "+f"(c[1]), "+f"(c[2]), "+f"(c[3])
        : "r"(a0), "r"(a1), "r"(a2), "r"(a3), "r"(b0), "r"(b1));
}
__device__ __forceinline__ void mma_f16c16(uint32& c0, uint32& c1,
    uint32 a0, uint32 a1, uint32 a2, uint32 a3, uint32 b0, uint32 b1)
{
    asm volatile(
        "mma.sync.aligned.m16n8k16.row.col.f16.f16.f16.f16 "
        "{%0,%1}, {%2,%3,%4,%5}, {%6,%7}, {%0,%1};"
        : "+r"(c0), "+r"(c1)
        : "r"(a0), "r"(a1), "r"(a2), "r"(a3), "r"(b0), "r"(b1));
}
__device__ __forceinline__ uint32 smem_u32(const void* p) {
    uint32 a;
    asm("{ .reg .u64 t; cvta.to.shared.u64 t, %1; cvt.u32.u64 %0, t; }" : "=r"(a) : "l"(p));
    return a;
}
#define CP_ASYNC16(dst, src) \
    asm volatile("cp.async.ca.shared.global [%0], [%1], 16;" :: "r"(dst), "l"(src))
#define CP_COMMIT() asm volatile("cp.async.commit_group;" ::: "memory")
#define CP_WAIT(N)  asm volatile("cp.async.wait_group %0;" :: "n"(N) : "memory")

// fp16 intermediates (q pre-scaled by scale*log2e; v stored transposed [b][h][kv])
__device__ __half g_qh[BSZ * SEQ * HD];
__device__ __half g_kh[BSZ * SEQ * HD];
__device__ __half g_vt[BSZ * HD * SEQ];
__device__ float  g_cos[SEQ * 32];
__device__ float  g_sin[SEQ * 32];

// ---------------------------------------------------------------------------
// Kernel 0: RoPE cos/sin table
// ---------------------------------------------------------------------------
__global__ void rope_table_kernel()
{
    const int t = blockIdx.x * blockDim.x + threadIdx.x;
    if (t >= SEQ * 32) return;
    const int pos = t >> 5;
    const int pr  = t & 31;
    const float theta = expf((float)pr * -0.5756462732485114f);
    float sn, cs;
    sincosf((float)pos * theta, &sn, &cs);
    g_cos[t] = cs;
    g_sin[t] = sn;
}

// ---------------------------------------------------------------------------
// Kernel 1: QKV projection (fp16 HMMA) + RoPE; fp16 outputs (R14+, passing).
// ---------------------------------------------------------------------------
#define XW 20

__global__ __launch_bounds__(256) void qkv_rope_kernel(
    const float* __restrict__ x,
    const float* __restrict__ Wq,
    const float* __restrict__ Wk,
    const float* __restrict__ Wv)
{
    const int which = blockIdx.x;
    const float* __restrict__ W = (which == 0) ? Wq : ((which == 1) ? Wk : Wv);

    const int m0 = blockIdx.y * 128;

    __shared__ uint32 xs[2][128 * XW];
    __shared__ uint32 ws[2][64 * XW];

    const int tid    = threadIdx.x;
    const int lane   = tid & 31;
    const int wid    = tid >> 5;
    const int warp_m = wid & 3;
    const int warp_n = wid >> 2;
    const int lr = lane >> 2;
    const int lc = lane & 3;

    const int xrow = tid >> 3;
    const int xkq  = tid & 7;

    uint2 rx[4], rw[2];

    float c[2][4][4];
    #pragma unroll
    for (int mt = 0; mt < 2; mt++)
        #pragma unroll
        for (int nt = 0; nt < 4; nt++)
            #pragma unroll
            for (int r = 0; r < 4; r++) c[mt][nt][r] = 0.f;

    #pragma unroll
    for (int q = 0; q < 4; q++) {
        float4 t = *(const float4*)&x[(size_t)(m0 + xrow + q * 32) * EMB + xkq * 4];
        rx[q] = make_uint2(ph2(t.x, t.y), ph2(t.z, t.w));
    }
    #pragma unroll
    for (int q = 0; q < 2; q++) {
        float4 t = *(const float4*)&W[(size_t)(xrow + q * 32) * EMB + xkq * 4];
        rw[q] = make_uint2(ph2(t.x, t.y), ph2(t.z, t.w));
    }
    #pragma unroll
    for (int q = 0; q < 4; q++)
        *(uint2*)&xs[0][(xrow + q * 32) * XW + xkq * 2] = rx[q];
    #pragma unroll
    for (int q = 0; q < 2; q++)
        *(uint2*)&ws[0][(xrow + q * 32) * XW + xkq * 2] = rw[q];
    __syncthreads();

    const int NCH = EMB / 32;   // 24
    for (int ec = 0; ec < NCH; ec++) {
        const int cur = ec & 1;
        const bool more = (ec + 1 < NCH);
        if (more) {
            const int e1 = (ec + 1) * 32;
            #pragma unroll
            for (int q = 0; q < 4; q++) {
                float4 t = *(const float4*)&x[(size_t)(m0 + xrow + q * 32) * EMB + e1 + xkq * 4];
                rx[q] = make_uint2(ph2(t.x, t.y), ph2(t.z, t.w));
            }
            #pragma unroll
            for (int q = 0; q < 2; q++) {
                float4 t = *(const float4*)&W[(size_t)(xrow + q * 32) * EMB + e1 + xkq * 4];
                rw[q] = make_uint2(ph2(t.x, t.y), ph2(t.z, t.w));
            }
        }

        #pragma unroll
        for (int ks = 0; ks < 2; ks++) {
            const int kb = ks * 8;
            uint32 a[2][4];
            #pragma unroll
            for (int mt = 0; mt < 2; mt++) {
                const int rb = warp_m * 32 + mt * 16 + lr;
                a[mt][0] = xs[cur][rb * XW + kb + lc];
                a[mt][1] = xs[cur][(rb + 8) * XW + kb + lc];
                a[mt][2] = xs[cur][rb * XW + kb + lc + 4];
                a[mt][3] = xs[cur][(rb + 8) * XW + kb + lc + 4];
            }
            uint32 bb[4][2];
            #pragma unroll
            for (int nt = 0; nt < 4; nt++) {
                const int nb = warp_n * 32 + nt * 8 + lr;
                bb[nt][0] = ws[cur][nb * XW + kb + lc];
                bb[nt][1] = ws[cur][nb * XW + kb + lc + 4];
            }
            #pragma unroll
            for (int mt = 0; mt < 2; mt++)
                #pragma unroll
                for (int nt = 0; nt < 4; nt++)
                    mma_f16(c[mt][nt], a[mt][0], a[mt][1], a[mt][2], a[mt][3],
                            bb[nt][0], bb[nt][1]);
        }

        if (more) {
            const int nxt = cur ^ 1;
            #pragma unroll
            for (int q = 0; q < 4; q++)
                *(uint2*)&xs[nxt][(xrow + q * 32) * XW + xkq * 2] = rx[q];
            #pragma unroll
            for (int q = 0; q < 2; q++)
                *(uint2*)&ws[nxt][(xrow + q * 32) * XW + xkq * 2] = rw[q];
            __syncthreads();
        }
    }

    if (which < 2) {
        const float sc = (which == 0) ? (0.03608439182435161f * 1.4426950408889634f) : 1.0f;
        __half* outp = (which == 0) ? g_qh : g_kh;
        #pragma unroll
        for (int mt = 0; mt < 2; mt++) {
            const int r0 = m0 + warp_m * 32 + mt * 16 + lr;
            const int r1 = r0 + 8;
            const int p0 = r0 & (SEQ - 1);
            const int p1 = r1 & (SEQ - 1);
            #pragma unroll
            for (int nt = 0; nt < 4; nt++) {
                const int d0   = warp_n * 32 + nt * 8 + 2 * lc;
                const int pair = d0 >> 1;
                {
                    const float cs = g_cos[p0 * 32 + pair];
                    const float sn = g_sin[p0 * 32 + pair];
                    const float av = c[mt][nt][0], bv = c[mt][nt][1];
                    *(uint32*)&outp[(size_t)r0 * HD + d0] =
                        ph2((av * cs - bv * sn) * sc, (bv * cs + av * sn) * sc);
                }
                {
                    const float cs = g_cos[p1 * 32 + pair];
                    const float sn = g_sin[p1 * 32 + pair];
                    const float av = c[mt][nt][2], bv = c[mt][nt][3];
                    *(uint32*)&outp[(size_t)r1 * HD + d0] =
                        ph2((av * cs - bv * sn) * sc, (bv * cs + av * sn) * sc);
                }
            }
        }
    } else {
        #pragma unroll
        for (int mt = 0; mt < 2; mt++) {
            const int r0  = m0 + warp_m * 32 + mt * 16 + lr;
            const int b   = r0 >> 10;
            const int kv0 = r0 & (SEQ - 1);
            __half* vb = g_vt + (size_t)b * HD * SEQ;
            #pragma unroll
            for (int nt = 0; nt < 4; nt++) {
                const int d0 = warp_n * 32 + nt * 8 + 2 * lc;
                vb[(size_t)d0 * SEQ + kv0]           = __float2half_rn(c[mt][nt][0]);
                vb[(size_t)(d0 + 1) * SEQ + kv0]     = __float2half_rn(c[mt][nt][1]);
                vb[(size_t)d0 * SEQ + kv0 + 8]       = __float2half_rn(c[mt][nt][2]);
                vb[(size_t)(d0 + 1) * SEQ + kv0 + 8] = __float2half_rn(c[mt][nt][3]);
            }
        }
    }
}

// ---------------------------------------------------------------------------
// Kernel 2: causal flash attention — 128-wide KV chunks (one softmax per 128
//   columns), fp16 S, cp.async staging, register P, ones-MMA row sums.
//   Smem: K [2][128][36w] + V [2][64][72w] = 73728 B -> 3 CTAs/SM.
// ---------------------------------------------------------------------------
#define KW 36    // K row stride (words)
#define VW 72    // V row stride (words)
#define ONE2 0x3C003C00u
#define NINF16 0xFC00u

__global__ __launch_bounds__(128, 3) void attn_kernel(float* __restrict__ out)
{
    extern __shared__ uint32 smu[];
    uint32* Ks = smu;                     // [2][128 kv][36w] fp16 [kv][h]
    uint32* Vp = Ks + 2 * 128 * KW;       // [2][64 h][72w]   fp16 [h][kvpair]
    const uint32 ks_base = smem_u32(Ks);
    const uint32 vp_base = smem_u32(Vp);

    const int b  = blockIdx.y;
    const int qt = (SEQ / 64 - 1) - blockIdx.x;   // largest work first
    const int q0 = qt * 64;

    const __half* __restrict__ qh = g_qh + ((size_t)b * SEQ + q0) * HD;
    const __half* __restrict__ kh = g_kh + (size_t)b * SEQ * HD;
    const __half* __restrict__ vt = g_vt + (size_t)b * HD * SEQ;

    const int tid  = threadIdx.x;
    const int lane = tid & 31;
    const int w    = tid >> 5;
    const int lr   = lane >> 2;
    const int lc   = lane & 3;

    // K staging: 128 rows x 8 segs; V staging: 64 rows x 16 segs
    const int krow = tid >> 3, kseg = tid & 7;

    // ---- Q fragments (pre-scaled fp16, direct global loads) ----
    uint32 qa[4][4];
    {
        const __half* q0p = qh + (size_t)(w * 16 + lr) * HD;
        const __half* q1p = q0p + 8 * HD;
        #pragma unroll
        for (int ks = 0; ks < 4; ks++) {
            const int k = ks * 16 + 2 * lc;
            qa[ks][0] = *(const uint32*)&q0p[k];
            qa[ks][1] = *(const uint32*)&q1p[k];
            qa[ks][2] = *(const uint32*)&q0p[k + 8];
            qa[ks][3] = *(const uint32*)&q1p[k + 8];
        }
    }

    const int NC = qt / 2 + 1;   // 128-wide chunks covering kv in [0, q0+64)

    // ---- stage chunk c into buffer buf ----
    auto stage = [&](int c, int buf) {
        const int kv0 = c * 128;
        const uint32 kb = ks_base + (uint32)(buf * 128 * 144);
        const uint32 vb = vp_base + (uint32)(buf * 64 * 288);
        #pragma unroll
        for (int j = 0; j < 8; j++) {
            const int r = krow + j * 16;                  // 0..127
            CP_ASYNC16(kb + (uint32)(r * 144 + kseg * 16),
                       (const char*)&kh[(size_t)(kv0 + r) * HD + kseg * 8]);
        }
        #pragma unroll
        for (int j = 0; j < 8; j++) {
            const int p = tid + j * 128;                  // 0..1023
            const int h = p >> 4, seg = p & 15;
            CP_ASYNC16(vb + (uint32)(h * 288 + seg * 16),
                       (const char*)&vt[(size_t)h * SEQ + kv0 + seg * 8]);
        }
        CP_COMMIT();
    };

    stage(0, 0);
    if (NC > 1) stage(1, 1);

    float m_r[2] = {-1e30f, -1e30f};
    float l_r[2] = {0.f, 0.f};
    float o[8][4];
    #pragma unroll
    for (int nt = 0; nt < 8; nt++)
        #pragma unroll
        for (int r = 0; r < 4; r++) o[nt][r] = 0.f;

    const int row0 = q0 + w * 16 + lr;
    const int row1 = row0 + 8;

    for (int t = 0; t < NC; t++) {
        const int cur = t & 1;
        uint32* Kc = Ks + cur * 128 * KW;
        uint32* Vc = Vp + cur * 64 * VW;

        if (t + 1 < NC) { CP_WAIT(1); } else { CP_WAIT(0); }
        __syncthreads();

        // ---- S = Q K^T over 128 columns (fp16 C, log2 domain) ----
        uint32 s2[16][2];
        #pragma unroll
        for (int nt = 0; nt < 16; nt++) { s2[nt][0] = 0u; s2[nt][1] = 0u; }

        #pragma unroll
        for (int ks = 0; ks < 4; ks++) {
            const int kb = ks * 8;
            #pragma unroll
            for (int nt = 0; nt < 16; nt++) {
                const int nb = nt * 8 + lr;
                const uint32 b0 = Kc[nb * KW + kb + lc];
                const uint32 b1 = Kc[nb * KW + kb + lc + 4];
                mma_f16c16(s2[nt][0], s2[nt][1],
                           qa[ks][0], qa[ks][1], qa[ks][2], qa[ks][3], b0, b1);
            }
        }

        // causal mask — only the last chunk can cross the diagonal
        if (t == NC - 1) {
            #pragma unroll
            for (int nt = 0; nt < 16; nt++) {
                const int col = t * 128 + nt * 8 + 2 * lc;
                __half2 v0 = *(__half2*)&s2[nt][0];
                __half2 v1 = *(__half2*)&s2[nt][1];
                if (col     > row0) v0.x = __ushort_as_half((unsigned short)NINF16);
                if (col + 1 > row0) v0.y = __ushort_as_half((unsigned short)NINF16);
                if (col     > row1) v1.x = __ushort_as_half((unsigned short)NINF16);
                if (col + 1 > row1) v1.y = __ushort_as_half((unsigned short)NINF16);
                *(__half2*)&s2[nt][0] = v0;
                *(__half2*)&s2[nt][1] = v1;
            }
        }

        // ---- online softmax over 128 columns ----
        __half2 pm0 = *(__half2*)&s2[0][0];
        __half2 pm1 = *(__half2*)&s2[0][1];
        #pragma unroll
        for (int nt = 1; nt < 16; nt++) {
            pm0 = __hmax2(pm0, *(__half2*)&s2[nt][0]);
            pm1 = __hmax2(pm1, *(__half2*)&s2[nt][1]);
        }
        float rm0 = __half2float(__hmax(pm0.x, pm0.y));
        float rm1 = __half2float(__hmax(pm1.x, pm1.y));
        rm0 = fmaxf(rm0, __shfl_xor_sync(0xffffffffu, rm0, 1));
        rm0 = fmaxf(rm0, __shfl_xor_sync(0xffffffffu, rm0, 2));
        rm1 = fmaxf(rm1, __shfl_xor_sync(0xffffffffu, rm1, 1));
        rm1 = fmaxf(rm1, __shfl_xor_sync(0xffffffffu, rm1, 2));

        const float mnew0 = fmaxf(m_r[0], rm0);
        const float mnew1 = fmaxf(m_r[1], rm1);
        const float alpha0 = exp2f(m_r[0] - mnew0);
        const float alpha1 = exp2f(m_r[1] - mnew1);
        m_r[0] = mnew0; m_r[1] = mnew1;

        const __half2 mh0 = __float2half2_rn(mnew0);
        const __half2 mh1 = __float2half2_rn(mnew1);

        // P = exp2(s - m) in packed fp16 (masked entries -> exp2(-inf) = 0)
        uint32 pA[16][2];
        #pragma unroll
        for (int nt = 0; nt < 16; nt++) {
            __half2 d0 = __hsub2(*(__half2*)&s2[nt][0], mh0);
            __half2 d1 = __hsub2(*(__half2*)&s2[nt][1], mh1);
            pA[nt][0] = h2exp2(*(uint32*)&d0);
            pA[nt][1] = h2exp2(*(uint32*)&d1);
        }

        // row sums via ones-MMA
        float rsum[4] = {0.f, 0.f, 0.f, 0.f};
        #pragma unroll
        for (int ks = 0; ks < 8; ks++)
            mma_f16(rsum, pA[2 * ks][0], pA[2 * ks][1],
                    pA[2 * ks + 1][0], pA[2 * ks + 1][1], ONE2, ONE2);
        l_r[0] = l_r[0] * alpha0 + rsum[0];
        l_r[1] = l_r[1] * alpha1 + rsum[2];

        if (__any_sync(0xffffffffu, (alpha0 < 1.0f) | (alpha1 < 1.0f))) {
            #pragma unroll
            for (int nt = 0; nt < 8; nt++) {
                o[nt][0] *= alpha0; o[nt][1] *= alpha0;
                o[nt][2] *= alpha1; o[nt][3] *= alpha1;
            }
        }

        // ---- O += P V over 128 kv ----
        #pragma unroll
        for (int ks = 0; ks < 8; ks++) {
            const int kb = ks * 8;
            const uint32 a0 = pA[2 * ks][0];
            const uint32 a1 = pA[2 * ks][1];
            const uint32 a2 = pA[2 * ks + 1][0];
            const uint32 a3 = pA[2 * ks + 1][1];
            #pragma unroll
            for (int nt = 0; nt < 8; nt++) {
                const int nb = nt * 8 + lr;
                const uint32 b0 = Vc[nb * VW + kb + lc];
                const uint32 b1 = Vc[nb * VW + kb + lc + 4];
                mma_f16(o[nt], a0, a1, a2, a3, b0, b1);
            }
        }

        __syncthreads();   // reads of buffer `cur` done before restage

        if (t + 2 < NC) stage(t + 2, cur);
    }

    const float il0 = 1.0f / l_r[0];
    const float il1 = 1.0f / l_r[1];
    #pragma unroll
    for (int nt = 0; nt < 8; nt++) {
        const int d0 = nt * 8 + 2 * lc;
        *(ull*)&out[((size_t)b * SEQ + row0) * HD + d0] = pk2(o[nt][0] * il0, o[nt][1] * il0);
        *(ull*)&out[((size_t)b * SEQ + row1) * HD + d0] = pk2(o[nt][2] * il1, o[nt][3] * il1);
    }
}

extern "C" void kernel_launch(void* const* d_in, const int* in_sizes, int n_in,
                              void* d_out, int out_size)
{
    const float* x  = (const float*)d_in[0];
    const float* Wq = (const float*)d_in[1];
    const float* Wk = (const float*)d_in[2];
    const float* Wv = (const float*)d_in[3];
    float* out = (float*)d_out;

    rope_table_kernel<<<(SEQ * 32 + 255) / 256, 256>>>();

    dim3 g1(3, (BSZ * SEQ) / 128);
    qkv_rope_kernel<<<g1, 256>>>(x, Wq, Wk, Wv);

    const int smem = (2 * 128 * KW + 2 * 64 * VW) * (int)sizeof(uint32);   // 73728 B
    cudaFuncSetAttribute(attn_kernel, cudaFuncAttributeMaxDynamicSharedMemorySize, smem);
    dim3 g2(SEQ / 64, BSZ);
    attn_kernel<<<g2, 128, smem>>>(out);
}